// round 1
// baseline (speedup 1.0000x reference)
#include <cuda_runtime.h>
#include <math.h>

#define BATCH  16384
#define INPUT  256
#define HIDDEN 512
#define OUTPUT 128
#define NITER  15

// ---------------- device scratch (static allocation, allowed) ----------------
__device__ float g_A  [BATCH * HIDDEN];   // rho(x)@W1 + b_h  (precomputed once)
__device__ float g_h0 [BATCH * HIDDEN];
__device__ float g_h1 [BATCH * HIDDEN];
__device__ float g_mh [BATCH * HIDDEN];
__device__ float g_vh [BATCH * HIDDEN];
__device__ float g_o0 [BATCH * OUTPUT];
__device__ float g_mo [BATCH * OUTPUT];
__device__ float g_vo [BATCH * OUTPUT];
__device__ float g_W2T[OUTPUT * HIDDEN];  // W2T[k][j] = W2[j][k]

// ---------------- helpers ----------------
__device__ __forceinline__ float drho(float s) {
    // d/ds clip(s,0,1) with JAX maximum/minimum balanced-eq tie rule: 0.5 at s==0 or s==1
    return (s > 0.f && s < 1.f) ? 1.f : ((s == 0.f || s == 1.f) ? 0.5f : 0.f);
}

__device__ __forceinline__ float adam_step(float pv, float term,
                                           float b1t, float b2t,
                                           float& mio, float& vio) {
    float g  = pv - drho(pv) * term;
    float mn = 0.9f   * mio + 0.1f   * g;
    float vn = 0.999f * vio + 0.001f * (g * g);
    mio = mn; vio = vn;
    float mh = mn / b1t;           // b1t = 1 - 0.9^t
    float vh = vn / b2t;           // b2t = 1 - 0.999^t
    return pv - 0.01f * (mh / (sqrtf(vh) + 1e-8f));
}

__device__ __forceinline__ void unpack2(unsigned long long p, float& lo, float& hi) {
    asm("mov.b64 {%0, %1}, %2;" : "=f"(lo), "=f"(hi) : "l"(p));
}

// ---------------- fused GEMM (+ optional Adam epilogue) ----------------
// Computes  acc[b][n] = sum_k rho(Ain[b][k]) * W[k][n]   over a 128x128 tile.
// EPI==0: outC[b][n] = acc + bias[n]                      (used for A precompute)
// EPI==1: Adam on p with term = add[b][n] + acc           (h update; add = A)
// EPI==2: Adam on p with term = bias[n] + acc             (o update; bias = b_o)
constexpr int BM = 128, BN = 128, KC = 32, ASTR = 36;

template <int EPI>
__global__ __launch_bounds__(256, 2)
void gemm_fused(const float* __restrict__ Ain, const float* __restrict__ W,
                int Ktot, int Ntot,
                const float* __restrict__ add, const float* __restrict__ bias,
                const float* __restrict__ p_old, float* __restrict__ p_new,
                float* __restrict__ m, float* __restrict__ v,
                float* __restrict__ outC,
                float b1t, float b2t)
{
    __shared__ float a_s[BM * ASTR];   // [b][k], padded stride 36 (conflict-free)
    __shared__ float w_s[KC * BN];     // [k][n]

    const int tid = threadIdx.x;
    const int tx  = tid & 15;          // column group selector
    const int ty  = tid >> 4;          // row selector
    const int bm0 = blockIdx.x * BM;
    const int bn0 = blockIdx.y * BN;

    unsigned long long acc[8][4];      // 8 rows x 4 f32x2 pairs (= 8x8 fp32)
#pragma unroll
    for (int i = 0; i < 8; i++)
#pragma unroll
        for (int q = 0; q < 4; q++) acc[i][q] = 0ULL;

    const int ar = tid >> 3, ac = tid & 7;    // A-stage: 32 rows/pass, 8 float4 cols
    const int wr = tid >> 5, wc = tid & 31;   // W-stage: 8 rows/pass, 32 float4 cols

    for (int k0 = 0; k0 < Ktot; k0 += KC) {
#pragma unroll
        for (int p = 0; p < 4; ++p) {
            int row = ar + p * 32;
            float4 va = *reinterpret_cast<const float4*>(
                &Ain[(bm0 + row) * Ktot + k0 + ac * 4]);
            float4 r;
            r.x = __saturatef(va.x); r.y = __saturatef(va.y);
            r.z = __saturatef(va.z); r.w = __saturatef(va.w);
            *reinterpret_cast<float4*>(&a_s[row * ASTR + ac * 4]) = r;
        }
#pragma unroll
        for (int p = 0; p < 4; ++p) {
            int row = wr + p * 8;
            float4 vw = *reinterpret_cast<const float4*>(
                &W[(k0 + row) * Ntot + bn0 + wc * 4]);
            *reinterpret_cast<float4*>(&w_s[row * BN + wc * 4]) = vw;
        }
        __syncthreads();

#pragma unroll
        for (int kk = 0; kk < KC; ++kk) {
            unsigned long long a2[8], wp[4];
#pragma unroll
            for (int i = 0; i < 8; i++) {
                float av = a_s[(ty + 16 * i) * ASTR + kk];
                asm("mov.b64 %0, {%1, %1};" : "=l"(a2[i]) : "f"(av));
            }
            float4 w0 = *reinterpret_cast<const float4*>(&w_s[kk * BN + tx * 4]);
            float4 w1 = *reinterpret_cast<const float4*>(&w_s[kk * BN + 64 + tx * 4]);
            asm("mov.b64 %0, {%1, %2};" : "=l"(wp[0]) : "f"(w0.x), "f"(w0.y));
            asm("mov.b64 %0, {%1, %2};" : "=l"(wp[1]) : "f"(w0.z), "f"(w0.w));
            asm("mov.b64 %0, {%1, %2};" : "=l"(wp[2]) : "f"(w1.x), "f"(w1.y));
            asm("mov.b64 %0, {%1, %2};" : "=l"(wp[3]) : "f"(w1.z), "f"(w1.w));
#pragma unroll
            for (int i = 0; i < 8; i++)
#pragma unroll
                for (int q = 0; q < 4; q++)
                    asm("fma.rn.f32x2 %0, %1, %2, %0;"
                        : "+l"(acc[i][q]) : "l"(a2[i]), "l"(wp[q]));
        }
        __syncthreads();
    }

    // ---------------- epilogue ----------------
#pragma unroll
    for (int i = 0; i < 8; i++) {
        int row = bm0 + ty + 16 * i;
#pragma unroll
        for (int gsel = 0; gsel < 2; gsel++) {
            int col = bn0 + gsel * 64 + tx * 4;
            int idx = row * Ntot + col;
            float c0, c1, c2, c3;
            unpack2(acc[i][2 * gsel],     c0, c1);
            unpack2(acc[i][2 * gsel + 1], c2, c3);

            if (EPI == 0) {
                float4 bb = *reinterpret_cast<const float4*>(&bias[col]);
                float4 r; r.x = c0 + bb.x; r.y = c1 + bb.y;
                          r.z = c2 + bb.z; r.w = c3 + bb.w;
                *reinterpret_cast<float4*>(&outC[idx]) = r;
            } else {
                float4 t4;
                if (EPI == 1) {
                    float4 av = *reinterpret_cast<const float4*>(&add[idx]);
                    t4.x = av.x + c0; t4.y = av.y + c1;
                    t4.z = av.z + c2; t4.w = av.w + c3;
                } else {
                    float4 bb = *reinterpret_cast<const float4*>(&bias[col]);
                    t4.x = bb.x + c0; t4.y = bb.y + c1;
                    t4.z = bb.z + c2; t4.w = bb.w + c3;
                }
                float4 pv = *reinterpret_cast<const float4*>(&p_old[idx]);
                float4 mv = *reinterpret_cast<const float4*>(&m[idx]);
                float4 vv = *reinterpret_cast<const float4*>(&v[idx]);
                float4 pn;
                pn.x = adam_step(pv.x, t4.x, b1t, b2t, mv.x, vv.x);
                pn.y = adam_step(pv.y, t4.y, b1t, b2t, mv.y, vv.y);
                pn.z = adam_step(pv.z, t4.z, b1t, b2t, mv.z, vv.z);
                pn.w = adam_step(pv.w, t4.w, b1t, b2t, mv.w, vv.w);
                *reinterpret_cast<float4*>(&m[idx])     = mv;
                *reinterpret_cast<float4*>(&v[idx])     = vv;
                *reinterpret_cast<float4*>(&p_new[idx]) = pn;
            }
        }
    }
}

// ---------------- misc kernels ----------------
__global__ void init_zero_kernel() {
    int i = blockIdx.x * blockDim.x + threadIdx.x;      // float4 index
    const int NH4 = BATCH * HIDDEN / 4, NO4 = BATCH * OUTPUT / 4;
    float4 z = make_float4(0.f, 0.f, 0.f, 0.f);
    if (i < NH4) {
        reinterpret_cast<float4*>(g_h0)[i] = z;
        reinterpret_cast<float4*>(g_mh)[i] = z;
        reinterpret_cast<float4*>(g_vh)[i] = z;
    }
    if (i < NO4) {
        reinterpret_cast<float4*>(g_o0)[i] = z;
        reinterpret_cast<float4*>(g_mo)[i] = z;
        reinterpret_cast<float4*>(g_vo)[i] = z;
    }
}

__global__ void transpose_w2_kernel(const float* __restrict__ W2) {
    int t = blockIdx.x * blockDim.x + threadIdx.x;      // 0 .. 65535
    int j = t >> 7, k = t & 127;
    g_W2T[k * HIDDEN + j] = W2[t];
}

// ---------------- launch ----------------
extern "C" void kernel_launch(void* const* d_in, const int* in_sizes, int n_in,
                              void* d_out, int out_size) {
    (void)in_sizes; (void)n_in; (void)out_size;
    const float* x   = (const float*)d_in[0];
    const float* W1  = (const float*)d_in[1];
    const float* W2  = (const float*)d_in[2];
    const float* b_h = (const float*)d_in[4];
    const float* b_o = (const float*)d_in[5];
    // d_in[6] = num_iterations (always 15 per setup_inputs)

    float *A, *h0, *h1, *mh, *vh, *o0, *mo, *vo, *W2T;
    cudaGetSymbolAddress((void**)&A,   g_A);
    cudaGetSymbolAddress((void**)&h0,  g_h0);
    cudaGetSymbolAddress((void**)&h1,  g_h1);
    cudaGetSymbolAddress((void**)&mh,  g_mh);
    cudaGetSymbolAddress((void**)&vh,  g_vh);
    cudaGetSymbolAddress((void**)&o0,  g_o0);
    cudaGetSymbolAddress((void**)&mo,  g_mo);
    cudaGetSymbolAddress((void**)&vo,  g_vo);
    cudaGetSymbolAddress((void**)&W2T, g_W2T);

    init_zero_kernel<<<(BATCH * HIDDEN / 4 + 255) / 256, 256>>>();
    transpose_w2_kernel<<<(HIDDEN * OUTPUT) / 128, 128>>>(W2);

    // A = rho(x) @ W1 + b_h     (M=16384, K=256, N=512)
    gemm_fused<0><<<dim3(BATCH / BM, HIDDEN / BN), 256>>>(
        x, W1, INPUT, HIDDEN, nullptr, b_h,
        nullptr, nullptr, nullptr, nullptr, A, 1.f, 1.f);

    float* hbuf[2] = {h0, h1};
    float* obuf[2] = {o0, (float*)d_out};   // t odd writes obuf[1]; t=15 -> d_out

    for (int t = 1; t <= NITER; ++t) {
        int p = (t - 1) & 1;
        float b1t = 1.0f - powf(0.9f,   (float)t);
        float b2t = 1.0f - powf(0.999f, (float)t);

        // K1: D = rho(h_old)@W2 ; Adam update o  (K=512, N=128)
        gemm_fused<2><<<dim3(BATCH / BM, OUTPUT / BN), 256>>>(
            hbuf[p], W2, HIDDEN, OUTPUT, nullptr, b_o,
            obuf[p], obuf[1 - p], mo, vo, nullptr, b1t, b2t);

        // K2: C = rho(o_old)@W2T ; term = A + C ; Adam update h  (K=128, N=512)
        gemm_fused<1><<<dim3(BATCH / BM, HIDDEN / BN), 256>>>(
            obuf[p], W2T, OUTPUT, HIDDEN, A, nullptr,
            hbuf[p], hbuf[1 - p], mh, vh, nullptr, b1t, b2t);
    }
}

// round 3
// speedup vs baseline: 1.1264x; 1.1264x over previous
#include <cuda_runtime.h>
#include <cuda_bf16.h>
#include <math.h>
#include <stdint.h>

#define BATCH  16384
#define INPUT  256
#define HIDDEN 512
#define OUTPUT 128
#define NITER  15

// ---------------- device scratch ----------------
__device__ float g_A [BATCH * HIDDEN];
__device__ float g_h0[BATCH * HIDDEN];
__device__ float g_h1[BATCH * HIDDEN];
__device__ float g_mh[BATCH * HIDDEN];
__device__ float g_vh[BATCH * HIDDEN];
__device__ float g_o0[BATCH * OUTPUT];
__device__ float g_mo[BATCH * OUTPUT];
__device__ float g_vo[BATCH * OUTPUT];

// bf16 hi/lo weight tiles: each tile = 128 n-rows x 64 k-cols = 8192 bf16 = 16KB,
// pre-swizzled (XOR-128 on 128B rows) so kernel loads are straight 16B copies.
__device__ __nv_bfloat16 g_W2h_hi[8  * 8192];  // B_h[n][k]=W2[n][k]: 4 ntiles x 2 kchunks
__device__ __nv_bfloat16 g_W2h_lo[8  * 8192];
__device__ __nv_bfloat16 g_W2o_hi[8  * 8192];  // B_o[n][k]=W2[k][n]: 1 ntile x 8 kchunks
__device__ __nv_bfloat16 g_W2o_lo[8  * 8192];
__device__ __nv_bfloat16 g_W1T_hi[16 * 8192];  // B_A[n][k]=W1[k][n]: 4 ntiles x 4 kchunks
__device__ __nv_bfloat16 g_W1T_lo[16 * 8192];

// ---------------- PTX helpers (all legal at compute_103) ----------------
__device__ __forceinline__ uint32_t smem_u32(const void* p) {
    uint32_t a;
    asm("{ .reg .u64 t; cvta.to.shared.u64 t, %1; cvt.u32.u64 %0, t; }" : "=r"(a) : "l"(p));
    return a;
}
__device__ __forceinline__ void ldsm4(uint32_t* r, uint32_t a) {
    asm volatile("ldmatrix.sync.aligned.m8n8.x4.shared.b16 {%0,%1,%2,%3}, [%4];"
                 : "=r"(r[0]), "=r"(r[1]), "=r"(r[2]), "=r"(r[3]) : "r"(a));
}
__device__ __forceinline__ void mma_bf16(float* c, const uint32_t* a, const uint32_t* b) {
    asm volatile("mma.sync.aligned.m16n8k16.row.col.f32.bf16.bf16.f32 "
                 "{%0,%1,%2,%3}, {%4,%5,%6,%7}, {%8,%9}, {%0,%1,%2,%3};"
                 : "+f"(c[0]), "+f"(c[1]), "+f"(c[2]), "+f"(c[3])
                 : "r"(a[0]), "r"(a[1]), "r"(a[2]), "r"(a[3]), "r"(b[0]), "r"(b[1]));
}
#define CP_ASYNC16(dst, src) asm volatile("cp.async.cg.shared.global [%0], [%1], 16;" :: "r"(dst), "l"(src) : "memory")
#define CP_COMMIT()          asm volatile("cp.async.commit_group;" ::: "memory")
#define CP_WAIT0()           asm volatile("cp.async.wait_group 0;" ::: "memory")

// ---------------- tile layout: 128 rows x 64 bf16 cols, 128B rows, XOR swizzle ----
__device__ __host__ __forceinline__ uint32_t swz(int r, int c) {   // c in bf16 elems
    uint32_t off = (uint32_t)((r >> 3) * 1024 + (r & 7) * 128 + c * 2);
    return off ^ ((off >> 3) & 0x70);
}

// smem layout (dynamic): A_hi 0, A_lo 16K, B double buffer at 32K/64K (hi,lo inside)
#define SM_AH   0
#define SM_AL   16384
#define SM_B(b) (32768 + (b) * 32768)
#define SMEM_TOTAL 98304

// ---------------- math ----------------
__device__ __forceinline__ float drho(float s) {
    return (s > 0.f && s < 1.f) ? 1.f : ((s == 0.f || s == 1.f) ? 0.5f : 0.f);
}
__device__ __forceinline__ float adam_step(float pv, float term, float b1t, float b2t,
                                           float& mio, float& vio) {
    float g  = pv - drho(pv) * term;
    float mn = 0.9f   * mio + 0.1f   * g;
    float vn = 0.999f * vio + 0.001f * (g * g);
    mio = mn; vio = vn;
    return pv - 0.01f * ((mn / b1t) / (sqrtf(vn / b2t) + 1e-8f));
}
__device__ __forceinline__ void split4(float4 v, uint2& hi, uint2& lo) {
    float s0 = __saturatef(v.x), s1 = __saturatef(v.y);
    float s2 = __saturatef(v.z), s3 = __saturatef(v.w);
    __nv_bfloat16 h0 = __float2bfloat16_rn(s0), h1 = __float2bfloat16_rn(s1);
    __nv_bfloat16 h2 = __float2bfloat16_rn(s2), h3 = __float2bfloat16_rn(s3);
    __nv_bfloat16 l0 = __float2bfloat16_rn(s0 - __bfloat162float(h0));
    __nv_bfloat16 l1 = __float2bfloat16_rn(s1 - __bfloat162float(h1));
    __nv_bfloat16 l2 = __float2bfloat16_rn(s2 - __bfloat162float(h2));
    __nv_bfloat16 l3 = __float2bfloat16_rn(s3 - __bfloat162float(h3));
    hi.x = ((uint32_t)__bfloat16_as_ushort(h1) << 16) | __bfloat16_as_ushort(h0);
    hi.y = ((uint32_t)__bfloat16_as_ushort(h3) << 16) | __bfloat16_as_ushort(h2);
    lo.x = ((uint32_t)__bfloat16_as_ushort(l1) << 16) | __bfloat16_as_ushort(l0);
    lo.y = ((uint32_t)__bfloat16_as_ushort(l3) << 16) | __bfloat16_as_ushort(l2);
}

// ---------------- mainloop: acc += rho(state)[128xK] @ B[Kx128] ----------------
__device__ __forceinline__ void mainloop(char* sm, uint32_t smb,
                                         const float* __restrict__ state, int sstride, int bm0,
                                         const __nv_bfloat16* __restrict__ whb,
                                         const __nv_bfloat16* __restrict__ wlb,
                                         int nchunks, int tid, float acc[2][8][4]) {
    const int lane = tid & 31, wid = tid >> 5, wm = wid & 3, wn = wid >> 2;

    // stage chunk 0: state -> split -> smem A ; weights -> cp.async B buf0
    {
#pragma unroll
        for (int i = 0; i < 8; i++) {
            int idx = tid + i * 256, r = idx >> 4, c4 = idx & 15;
            float4 v = *reinterpret_cast<const float4*>(
                &state[(size_t)(bm0 + r) * sstride + c4 * 4]);
            uint2 hi, lo; split4(v, hi, lo);
            uint32_t off = swz(r, c4 * 4);
            *reinterpret_cast<uint2*>(sm + SM_AH + off) = hi;
            *reinterpret_cast<uint2*>(sm + SM_AL + off) = lo;
        }
#pragma unroll
        for (int i = 0; i < 4; i++) {
            int e = tid + i * 256;
            CP_ASYNC16(smb + SM_B(0) + e * 16,          whb + e * 8);
            CP_ASYNC16(smb + SM_B(0) + 16384 + e * 16,  wlb + e * 8);
        }
        CP_COMMIT();
    }

    for (int c = 0; c < nchunks; ++c) {
        CP_WAIT0();
        __syncthreads();                       // chunk c fully staged
        const bool more = (c + 1 < nchunks);
        float4 v[8];
        if (more) {
            // issue next state LDGs (consumed after the mma block)
            int kc0 = (c + 1) * 64;
#pragma unroll
            for (int i = 0; i < 8; i++) {
                int idx = tid + i * 256, r = idx >> 4, c4 = idx & 15;
                v[i] = *reinterpret_cast<const float4*>(
                    &state[(size_t)(bm0 + r) * sstride + kc0 + c4 * 4]);
            }
            uint32_t bb = SM_B((c + 1) & 1);
            const __nv_bfloat16* wh = whb + (size_t)(c + 1) * 8192;
            const __nv_bfloat16* wl = wlb + (size_t)(c + 1) * 8192;
#pragma unroll
            for (int i = 0; i < 4; i++) {
                int e = tid + i * 256;
                CP_ASYNC16(smb + bb + e * 16,         wh + e * 8);
                CP_ASYNC16(smb + bb + 16384 + e * 16, wl + e * 8);
            }
            CP_COMMIT();
        }

        // -------- mma over chunk c (K=64, 4 k16 steps) --------
        const uint32_t bb = SM_B(c & 1);
#pragma unroll
        for (int ks = 0; ks < 4; ++ks) {
            uint32_t Ah[2][4], Al[2][4], Bh[4][4], Bl[4][4];
            int ac = ks * 16 + (lane >> 4) * 8;
#pragma unroll
            for (int mt = 0; mt < 2; ++mt) {
                uint32_t o = swz(wm * 32 + mt * 16 + (lane & 15), ac);
                ldsm4(Ah[mt], smb + SM_AH + o);
                ldsm4(Al[mt], smb + SM_AL + o);
            }
            int bc = ks * 16 + ((lane >> 3) & 1) * 8;
            int brow = wn * 64 + ((lane >> 4) & 1) * 8 + (lane & 7);
#pragma unroll
            for (int bt = 0; bt < 4; ++bt) {
                uint32_t o = swz(brow + bt * 16, bc);
                ldsm4(Bh[bt], smb + bb + o);
                ldsm4(Bl[bt], smb + bb + 16384 + o);
            }
#pragma unroll
            for (int mt = 0; mt < 2; ++mt)
#pragma unroll
                for (int bt = 0; bt < 4; ++bt) {
                    mma_bf16(acc[mt][bt * 2],     Ah[mt], &Bh[bt][0]);
                    mma_bf16(acc[mt][bt * 2],     Ah[mt], &Bl[bt][0]);
                    mma_bf16(acc[mt][bt * 2],     Al[mt], &Bh[bt][0]);
                    mma_bf16(acc[mt][bt * 2 + 1], Ah[mt], &Bh[bt][2]);
                    mma_bf16(acc[mt][bt * 2 + 1], Ah[mt], &Bl[bt][2]);
                    mma_bf16(acc[mt][bt * 2 + 1], Al[mt], &Bh[bt][2]);
                }
        }
        __syncthreads();                       // all warps done reading A
        if (more) {
#pragma unroll
            for (int i = 0; i < 8; i++) {
                int idx = tid + i * 256, r = idx >> 4, c4 = idx & 15;
                uint2 hi, lo; split4(v[i], hi, lo);
                uint32_t off = swz(r, c4 * 4);
                *reinterpret_cast<uint2*>(sm + SM_AH + off) = hi;
                *reinterpret_cast<uint2*>(sm + SM_AL + off) = lo;
            }
        }
    }
}

// ---------------- kernels ----------------
__global__ __launch_bounds__(256, 1)
void pre_kernel(const float* __restrict__ x, const float* __restrict__ b_h) {
    extern __shared__ __align__(128) char sm[];
    uint32_t smb = smem_u32(sm);
    const int tid = threadIdx.x, lane = tid & 31, wid = tid >> 5;
    const int wm = wid & 3, wn = wid >> 2;
    const int bid = blockIdx.x;
    const int bm0 = (bid >> 2) * 128, ntile = bid & 3;

    float acc[2][8][4];
#pragma unroll
    for (int a = 0; a < 2; a++)
#pragma unroll
        for (int b = 0; b < 8; b++)
#pragma unroll
            for (int q = 0; q < 4; q++) acc[a][b][q] = 0.f;

    mainloop(sm, smb, x, INPUT, bm0,
             g_W1T_hi + (size_t)ntile * 4 * 8192, g_W1T_lo + (size_t)ntile * 4 * 8192,
             4, tid, acc);

    const int r0 = bm0 + wm * 32 + (lane >> 2);
    const int cb0 = wn * 64 + (lane & 3) * 2;
#pragma unroll
    for (int mt = 0; mt < 2; ++mt)
#pragma unroll
        for (int nt = 0; nt < 8; ++nt)
#pragma unroll
            for (int hf = 0; hf < 2; ++hf) {
                int r = r0 + mt * 16 + hf * 8;
                int cc = cb0 + nt * 8;
                int col = ntile * 128 + cc;
                float2 bh = *reinterpret_cast<const float2*>(&b_h[col]);
                float2 out;
                out.x = acc[mt][nt][hf * 2]     + bh.x;
                out.y = acc[mt][nt][hf * 2 + 1] + bh.y;
                *reinterpret_cast<float2*>(&g_A[(size_t)r * HIDDEN + col]) = out;
            }
}

__global__ __launch_bounds__(256, 1)
void step_kernel(const float* __restrict__ h_old, const float* __restrict__ o_old,
                 float* __restrict__ h_new, float* __restrict__ o_new,
                 const float* __restrict__ b_o, float b1t, float b2t) {
    extern __shared__ __align__(128) char sm[];
    uint32_t smb = smem_u32(sm);
    const int tid = threadIdx.x, lane = tid & 31, wid = tid >> 5;
    const int wm = wid & 3, wn = wid >> 2;
    const int bid = blockIdx.x;

    float acc[2][8][4];
#pragma unroll
    for (int a = 0; a < 2; a++)
#pragma unroll
        for (int b = 0; b < 8; b++)
#pragma unroll
            for (int q = 0; q < 4; q++) acc[a][b][q] = 0.f;

    const int r0l = wm * 32 + (lane >> 2);
    const int cb0 = wn * 64 + (lane & 3) * 2;

    if (bid < 128) {
        // -------- o update: D = rho(h_old) @ W2o  (K=512, 8 chunks) --------
        const int bm0 = bid * 128;
        mainloop(sm, smb, h_old, HIDDEN, bm0, g_W2o_hi, g_W2o_lo, 8, tid, acc);
#pragma unroll
        for (int mt = 0; mt < 2; ++mt)
#pragma unroll
            for (int nt = 0; nt < 8; ++nt)
#pragma unroll
                for (int hf = 0; hf < 2; ++hf) {
                    int r = bm0 + r0l + mt * 16 + hf * 8;
                    int cc = cb0 + nt * 8;
                    size_t idx = (size_t)r * OUTPUT + cc;
                    float2 bo = *reinterpret_cast<const float2*>(&b_o[cc]);
                    float2 pv = *reinterpret_cast<const float2*>(&o_old[idx]);
                    float2 mv = *reinterpret_cast<const float2*>(&g_mo[idx]);
                    float2 vv = *reinterpret_cast<const float2*>(&g_vo[idx]);
                    float2 pn;
                    pn.x = adam_step(pv.x, bo.x + acc[mt][nt][hf * 2],     b1t, b2t, mv.x, vv.x);
                    pn.y = adam_step(pv.y, bo.y + acc[mt][nt][hf * 2 + 1], b1t, b2t, mv.y, vv.y);
                    *reinterpret_cast<float2*>(&g_mo[idx]) = mv;
                    *reinterpret_cast<float2*>(&g_vo[idx]) = vv;
                    *reinterpret_cast<float2*>(&o_new[idx]) = pn;
                }
    } else {
        // -------- h update: D = rho(o_old) @ W2h  (K=128, 2 chunks); term = A + D ----
        const int idx0 = bid - 128;
        const int bm0 = (idx0 >> 2) * 128, ntile = idx0 & 3;
        mainloop(sm, smb, o_old, OUTPUT, bm0,
                 g_W2h_hi + (size_t)ntile * 2 * 8192, g_W2h_lo + (size_t)ntile * 2 * 8192,
                 2, tid, acc);
#pragma unroll
        for (int mt = 0; mt < 2; ++mt)
#pragma unroll
            for (int nt = 0; nt < 8; ++nt)
#pragma unroll
                for (int hf = 0; hf < 2; ++hf) {
                    int r = bm0 + r0l + mt * 16 + hf * 8;
                    int col = ntile * 128 + cb0 + nt * 8;
                    size_t idx = (size_t)r * HIDDEN + col;
                    float2 av = *reinterpret_cast<const float2*>(&g_A[idx]);
                    float2 pv = *reinterpret_cast<const float2*>(&h_old[idx]);
                    float2 mv = *reinterpret_cast<const float2*>(&g_mh[idx]);
                    float2 vv = *reinterpret_cast<const float2*>(&g_vh[idx]);
                    float2 pn;
                    pn.x = adam_step(pv.x, av.x + acc[mt][nt][hf * 2],     b1t, b2t, mv.x, vv.x);
                    pn.y = adam_step(pv.y, av.y + acc[mt][nt][hf * 2 + 1], b1t, b2t, mv.y, vv.y);
                    *reinterpret_cast<float2*>(&g_mh[idx]) = mv;
                    *reinterpret_cast<float2*>(&g_vh[idx]) = vv;
                    *reinterpret_cast<float2*>(&h_new[idx]) = pn;
                }
    }
}

// ---------------- prep kernels ----------------
__global__ void init_zero_kernel() {
    int i = blockIdx.x * blockDim.x + threadIdx.x;
    const int NH4 = BATCH * HIDDEN / 4, NO4 = BATCH * OUTPUT / 4;
    float4 z = make_float4(0.f, 0.f, 0.f, 0.f);
    if (i < NH4) {
        reinterpret_cast<float4*>(g_h0)[i] = z;
        reinterpret_cast<float4*>(g_mh)[i] = z;
        reinterpret_cast<float4*>(g_vh)[i] = z;
    }
    if (i < NO4) {
        reinterpret_cast<float4*>(g_o0)[i] = z;
        reinterpret_cast<float4*>(g_mo)[i] = z;
        reinterpret_cast<float4*>(g_vo)[i] = z;
    }
}

__global__ void prep_weights(const float* __restrict__ W1, const float* __restrict__ W2) {
    int t = blockIdx.x * blockDim.x + threadIdx.x;   // 0 .. 262143
    float v;
    __nv_bfloat16 *hi, *lo;
    int tile, r, cl;
    if (t < 65536) {                    // W2h: B[n][k] = W2[n][k]
        tile = t >> 13; int e = t & 8191; r = e >> 6; cl = e & 63;
        int tn = tile >> 1, kc = tile & 1;
        v = W2[(size_t)(tn * 128 + r) * OUTPUT + kc * 64 + cl];
        hi = g_W2h_hi; lo = g_W2h_lo;
    } else if (t < 131072) {            // W2o: B[n][k] = W2[k][n]
        int t2 = t - 65536;
        tile = t2 >> 13; int e = t2 & 8191; r = e >> 6; cl = e & 63;
        v = W2[(size_t)(tile * 64 + cl) * OUTPUT + r];
        hi = g_W2o_hi; lo = g_W2o_lo;
    } else {                            // W1T: B[n][k] = W1[k][n]
        int t3 = t - 131072;
        tile = t3 >> 13; int e = t3 & 8191; r = e >> 6; cl = e & 63;
        int tn = tile >> 2, kc = tile & 3;
        v = W1[(size_t)(kc * 64 + cl) * HIDDEN + tn * 128 + r];
        hi = g_W1T_hi; lo = g_W1T_lo;
    }
    __nv_bfloat16 h = __float2bfloat16_rn(v);
    __nv_bfloat16 l = __float2bfloat16_rn(v - __bfloat162float(h));
    uint32_t off = swz(r, cl);
    *reinterpret_cast<__nv_bfloat16*>(reinterpret_cast<char*>(hi) + (size_t)tile * 16384 + off) = h;
    *reinterpret_cast<__nv_bfloat16*>(reinterpret_cast<char*>(lo) + (size_t)tile * 16384 + off) = l;
}

// ---------------- launch ----------------
extern "C" void kernel_launch(void* const* d_in, const int* in_sizes, int n_in,
                              void* d_out, int out_size) {
    (void)in_sizes; (void)n_in; (void)out_size;
    const float* x   = (const float*)d_in[0];
    const float* W1  = (const float*)d_in[1];
    const float* W2  = (const float*)d_in[2];
    const float* b_h = (const float*)d_in[4];
    const float* b_o = (const float*)d_in[5];

    cudaFuncSetAttribute(pre_kernel,  cudaFuncAttributeMaxDynamicSharedMemorySize, SMEM_TOTAL);
    cudaFuncSetAttribute(step_kernel, cudaFuncAttributeMaxDynamicSharedMemorySize, SMEM_TOTAL);

    float *h0, *h1, *o0;
    cudaGetSymbolAddress((void**)&h0, g_h0);
    cudaGetSymbolAddress((void**)&h1, g_h1);
    cudaGetSymbolAddress((void**)&o0, g_o0);

    init_zero_kernel<<<(BATCH * HIDDEN / 4 + 255) / 256, 256>>>();
    prep_weights<<<262144 / 256, 256>>>(W1, W2);
    pre_kernel<<<512, 256, SMEM_TOTAL>>>(x, b_h);

    float* hbuf[2] = {h0, h1};
    float* obuf[2] = {o0, (float*)d_out};   // t odd writes obuf[1]; t=15 -> d_out

    for (int t = 1; t <= NITER; ++t) {
        int p = (t - 1) & 1;
        float b1t = 1.0f - powf(0.9f,   (float)t);
        float b2t = 1.0f - powf(0.999f, (float)t);
        step_kernel<<<640, 256, SMEM_TOTAL>>>(hbuf[p], obuf[p], hbuf[1 - p], obuf[1 - p],
                                              b_o, b1t, b2t);
    }
}

// round 4
// speedup vs baseline: 1.2996x; 1.1538x over previous
#include <cuda_runtime.h>
#include <cuda_bf16.h>
#include <math.h>
#include <stdint.h>

#define BATCH  16384
#define INPUT  256
#define HIDDEN 512
#define OUTPUT 128
#define NITER  15

// ---------------- device scratch ----------------
__device__ float g_A [BATCH * HIDDEN];
__device__ float g_h0[BATCH * HIDDEN];
__device__ float g_h1[BATCH * HIDDEN];
__device__ float g_mh[BATCH * HIDDEN];
__device__ float g_vh[BATCH * HIDDEN];
__device__ float g_o0[BATCH * OUTPUT];
__device__ float g_mo[BATCH * OUTPUT];
__device__ float g_vo[BATCH * OUTPUT];

// 3-way-split bf16 weight tiles (hi/mid/lo). Tile = 128 n-rows x 64 k-cols,
// pre-swizzled (XOR-128 on 128B rows) so kernel loads are straight 16B copies.
__device__ __nv_bfloat16 g_W2h_h[8  * 8192], g_W2h_m[8  * 8192], g_W2h_l[8  * 8192];
__device__ __nv_bfloat16 g_W2o_h[8  * 8192], g_W2o_m[8  * 8192], g_W2o_l[8  * 8192];
__device__ __nv_bfloat16 g_W1T_h[16 * 8192], g_W1T_m[16 * 8192], g_W1T_l[16 * 8192];

// ---------------- PTX helpers ----------------
__device__ __forceinline__ uint32_t smem_u32(const void* p) {
    uint32_t a;
    asm("{ .reg .u64 t; cvta.to.shared.u64 t, %1; cvt.u32.u64 %0, t; }" : "=r"(a) : "l"(p));
    return a;
}
__device__ __forceinline__ void ldsm4(uint32_t* r, uint32_t a) {
    asm volatile("ldmatrix.sync.aligned.m8n8.x4.shared.b16 {%0,%1,%2,%3}, [%4];"
                 : "=r"(r[0]), "=r"(r[1]), "=r"(r[2]), "=r"(r[3]) : "r"(a));
}
__device__ __forceinline__ void mma_bf16(float* c, const uint32_t* a, const uint32_t* b) {
    asm volatile("mma.sync.aligned.m16n8k16.row.col.f32.bf16.bf16.f32 "
                 "{%0,%1,%2,%3}, {%4,%5,%6,%7}, {%8,%9}, {%0,%1,%2,%3};"
                 : "+f"(c[0]), "+f"(c[1]), "+f"(c[2]), "+f"(c[3])
                 : "r"(a[0]), "r"(a[1]), "r"(a[2]), "r"(a[3]), "r"(b[0]), "r"(b[1]));
}
#define CP_ASYNC16(dst, src) asm volatile("cp.async.cg.shared.global [%0], [%1], 16;" :: "r"(dst), "l"(src) : "memory")
#define CP_COMMIT()          asm volatile("cp.async.commit_group;" ::: "memory")
#define CP_WAIT0()           asm volatile("cp.async.wait_group 0;" ::: "memory")

// ---------------- tile layout: 128 rows x 64 bf16 cols, 128B rows, XOR swizzle ----
__device__ __forceinline__ uint32_t swz(int r, int c) {   // c in bf16 elems
    uint32_t off = (uint32_t)((r >> 3) * 1024 + (r & 7) * 128 + c * 2);
    return off ^ ((off >> 3) & 0x70);
}

// smem: A tiles (hi,mid,lo) then B double buffer of (hi,mid,lo)
#define SM_A(v)      ((v) * 16384)
#define SM_B(bf, v)  (49152 + (bf) * 49152 + (v) * 16384)
#define SMEM_TOTAL   147456

// ---------------- math ----------------
__device__ __forceinline__ float drho(float s) {
    return (s > 0.f && s < 1.f) ? 1.f : ((s == 0.f || s == 1.f) ? 0.5f : 0.f);
}
__device__ __forceinline__ float adam_step(float pv, float term, float b1t, float b2t,
                                           float& mio, float& vio) {
    float g  = pv - drho(pv) * term;
    float mn = 0.9f   * mio + 0.1f   * g;
    float vn = 0.999f * vio + 0.001f * (g * g);
    mio = mn; vio = vn;
    return pv - 0.01f * ((mn / b1t) / (sqrtf(vn / b2t) + 1e-8f));
}
__device__ __forceinline__ uint32_t pack2(__nv_bfloat16 a, __nv_bfloat16 b) {
    return ((uint32_t)__bfloat16_as_ushort(b) << 16) | __bfloat16_as_ushort(a);
}
// 3-way bf16 split of saturated float4
__device__ __forceinline__ void split3(float4 v, uint2& H, uint2& M, uint2& L) {
    float s[4] = {__saturatef(v.x), __saturatef(v.y), __saturatef(v.z), __saturatef(v.w)};
    __nv_bfloat16 h[4], m[4], l[4];
#pragma unroll
    for (int i = 0; i < 4; i++) {
        h[i] = __float2bfloat16_rn(s[i]);
        float r1 = s[i] - __bfloat162float(h[i]);
        m[i] = __float2bfloat16_rn(r1);
        float r2 = r1 - __bfloat162float(m[i]);
        l[i] = __float2bfloat16_rn(r2);
    }
    H.x = pack2(h[0], h[1]); H.y = pack2(h[2], h[3]);
    M.x = pack2(m[0], m[1]); M.y = pack2(m[2], m[3]);
    L.x = pack2(l[0], l[1]); L.y = pack2(l[2], l[3]);
}

// ---------------- mainloop: acc += rho(state)[128xK] @ B[Kx128] (6-product) ------
// 512 threads, 16 warps; warp tile 32(m) x 32(n): wm = wid&3, wn = wid>>2.
__device__ __forceinline__ void mainloop(char* sm, uint32_t smb,
                                         const float* __restrict__ state, int sstride, int bm0,
                                         const __nv_bfloat16* __restrict__ wH,
                                         const __nv_bfloat16* __restrict__ wM,
                                         const __nv_bfloat16* __restrict__ wL,
                                         int nchunks, int tid, float acc[2][4][4]) {
    const int lane = tid & 31, wid = tid >> 5, wm = wid & 3, wn = wid >> 2;

    // stage chunk 0
    {
#pragma unroll
        for (int i = 0; i < 4; i++) {
            int idx = tid + i * 512, r = idx >> 4, c4 = idx & 15;
            float4 v = *reinterpret_cast<const float4*>(
                &state[(size_t)(bm0 + r) * sstride + c4 * 4]);
            uint2 H, M, L; split3(v, H, M, L);
            uint32_t off = swz(r, c4 * 4);
            *reinterpret_cast<uint2*>(sm + SM_A(0) + off) = H;
            *reinterpret_cast<uint2*>(sm + SM_A(1) + off) = M;
            *reinterpret_cast<uint2*>(sm + SM_A(2) + off) = L;
        }
#pragma unroll
        for (int i = 0; i < 2; i++) {
            int e = tid + i * 512;
            CP_ASYNC16(smb + SM_B(0, 0) + e * 16, wH + e * 8);
            CP_ASYNC16(smb + SM_B(0, 1) + e * 16, wM + e * 8);
            CP_ASYNC16(smb + SM_B(0, 2) + e * 16, wL + e * 8);
        }
        CP_COMMIT();
    }

    for (int c = 0; c < nchunks; ++c) {
        CP_WAIT0();
        __syncthreads();                       // chunk c fully staged
        const bool more = (c + 1 < nchunks);
        float4 v[4];
        if (more) {
            int kc0 = (c + 1) * 64;
#pragma unroll
            for (int i = 0; i < 4; i++) {
                int idx = tid + i * 512, r = idx >> 4, c4 = idx & 15;
                v[i] = *reinterpret_cast<const float4*>(
                    &state[(size_t)(bm0 + r) * sstride + kc0 + c4 * 4]);
            }
            int bb = (c + 1) & 1;
            size_t wo = (size_t)(c + 1) * 8192;
#pragma unroll
            for (int i = 0; i < 2; i++) {
                int e = tid + i * 512;
                CP_ASYNC16(smb + SM_B(bb, 0) + e * 16, wH + wo + e * 8);
                CP_ASYNC16(smb + SM_B(bb, 1) + e * 16, wM + wo + e * 8);
                CP_ASYNC16(smb + SM_B(bb, 2) + e * 16, wL + wo + e * 8);
            }
            CP_COMMIT();
        }

        // -------- mma over chunk c (K=64, 4 k16 steps), 6 products --------
        const int bb = c & 1;
#pragma unroll
        for (int ks = 0; ks < 4; ++ks) {
            uint32_t A[3][2][4], B[3][2][4];
            int ac = ks * 16 + (lane >> 4) * 8;
#pragma unroll
            for (int mt = 0; mt < 2; ++mt) {
                uint32_t o = swz(wm * 32 + mt * 16 + (lane & 15), ac);
                ldsm4(A[0][mt], smb + SM_A(0) + o);
                ldsm4(A[1][mt], smb + SM_A(1) + o);
                ldsm4(A[2][mt], smb + SM_A(2) + o);
            }
            int bc = ks * 16 + ((lane >> 3) & 1) * 8;
            int br = wn * 32 + ((lane >> 4) & 1) * 8 + (lane & 7);
#pragma unroll
            for (int bt = 0; bt < 2; ++bt) {
                uint32_t o = swz(br + bt * 16, bc);
                ldsm4(B[0][bt], smb + SM_B(bb, 0) + o);
                ldsm4(B[1][bt], smb + SM_B(bb, 1) + o);
                ldsm4(B[2][bt], smb + SM_B(bb, 2) + o);
            }
#pragma unroll
            for (int mt = 0; mt < 2; ++mt)
#pragma unroll
                for (int bt = 0; bt < 2; ++bt) {
                    float* c0 = acc[mt][bt * 2];
                    float* c1 = acc[mt][bt * 2 + 1];
                    mma_bf16(c0, A[0][mt], &B[0][bt][0]);  // hh
                    mma_bf16(c1, A[0][mt], &B[0][bt][2]);
                    mma_bf16(c0, A[0][mt], &B[1][bt][0]);  // hm
                    mma_bf16(c1, A[0][mt], &B[1][bt][2]);
                    mma_bf16(c0, A[1][mt], &B[0][bt][0]);  // mh
                    mma_bf16(c1, A[1][mt], &B[0][bt][2]);
                    mma_bf16(c0, A[0][mt], &B[2][bt][0]);  // hl
                    mma_bf16(c1, A[0][mt], &B[2][bt][2]);
                    mma_bf16(c0, A[2][mt], &B[0][bt][0]);  // lh
                    mma_bf16(c1, A[2][mt], &B[0][bt][2]);
                    mma_bf16(c0, A[1][mt], &B[1][bt][0]);  // mm
                    mma_bf16(c1, A[1][mt], &B[1][bt][2]);
                }
        }
        __syncthreads();                       // all warps done reading A
        if (more) {
#pragma unroll
            for (int i = 0; i < 4; i++) {
                int idx = tid + i * 512, r = idx >> 4, c4 = idx & 15;
                uint2 H, M, L; split3(v[i], H, M, L);
                uint32_t off = swz(r, c4 * 4);
                *reinterpret_cast<uint2*>(sm + SM_A(0) + off) = H;
                *reinterpret_cast<uint2*>(sm + SM_A(1) + off) = M;
                *reinterpret_cast<uint2*>(sm + SM_A(2) + off) = L;
            }
        }
    }
}

// ---------------- kernels ----------------
__global__ __launch_bounds__(512, 1)
void pre_kernel(const float* __restrict__ x, const float* __restrict__ b_h) {
    extern __shared__ __align__(128) char sm[];
    uint32_t smb = smem_u32(sm);
    const int tid = threadIdx.x, lane = tid & 31, wid = tid >> 5;
    const int wm = wid & 3, wn = wid >> 2;
    const int bid = blockIdx.x;
    const int bm0 = (bid >> 2) * 128, ntile = bid & 3;

    float acc[2][4][4];
#pragma unroll
    for (int a = 0; a < 2; a++)
#pragma unroll
        for (int b = 0; b < 4; b++)
#pragma unroll
            for (int q = 0; q < 4; q++) acc[a][b][q] = 0.f;

    size_t wo = (size_t)ntile * 4 * 8192;
    mainloop(sm, smb, x, INPUT, bm0, g_W1T_h + wo, g_W1T_m + wo, g_W1T_l + wo, 4, tid, acc);

#pragma unroll
    for (int mt = 0; mt < 2; ++mt)
#pragma unroll
        for (int j = 0; j < 4; ++j)
#pragma unroll
            for (int rr = 0; rr < 2; ++rr) {
                int r = bm0 + wm * 32 + mt * 16 + rr * 8 + (lane >> 2);
                int col = ntile * 128 + wn * 32 + j * 8 + (lane & 3) * 2;
                float2 bh = *reinterpret_cast<const float2*>(&b_h[col]);
                float2 out;
                out.x = acc[mt][j][rr * 2]     + bh.x;
                out.y = acc[mt][j][rr * 2 + 1] + bh.y;
                *reinterpret_cast<float2*>(&g_A[(size_t)r * HIDDEN + col]) = out;
            }
}

__global__ __launch_bounds__(512, 1)
void step_kernel(const float* __restrict__ h_old, const float* __restrict__ o_old,
                 float* __restrict__ h_new, float* __restrict__ o_new,
                 const float* __restrict__ b_o, float b1t, float b2t) {
    extern __shared__ __align__(128) char sm[];
    uint32_t smb = smem_u32(sm);
    const int tid = threadIdx.x, lane = tid & 31, wid = tid >> 5;
    const int wm = wid & 3, wn = wid >> 2;
    const int bid = blockIdx.x;

    float acc[2][4][4];
#pragma unroll
    for (int a = 0; a < 2; a++)
#pragma unroll
        for (int b = 0; b < 4; b++)
#pragma unroll
            for (int q = 0; q < 4; q++) acc[a][b][q] = 0.f;

    if (bid < 128) {
        // -------- o update: D = rho(h_old) @ W2o (K=512, 8 chunks) --------
        const int bm0 = bid * 128;
        mainloop(sm, smb, h_old, HIDDEN, bm0, g_W2o_h, g_W2o_m, g_W2o_l, 8, tid, acc);
#pragma unroll
        for (int mt = 0; mt < 2; ++mt)
#pragma unroll
            for (int j = 0; j < 4; ++j)
#pragma unroll
                for (int rr = 0; rr < 2; ++rr) {
                    int r = bm0 + wm * 32 + mt * 16 + rr * 8 + (lane >> 2);
                    int cc = wn * 32 + j * 8 + (lane & 3) * 2;
                    size_t idx = (size_t)r * OUTPUT + cc;
                    float2 bo = *reinterpret_cast<const float2*>(&b_o[cc]);
                    float2 pv = *reinterpret_cast<const float2*>(&o_old[idx]);
                    float2 mv = *reinterpret_cast<const float2*>(&g_mo[idx]);
                    float2 vv = *reinterpret_cast<const float2*>(&g_vo[idx]);
                    float2 pn;
                    pn.x = adam_step(pv.x, bo.x + acc[mt][j][rr * 2],     b1t, b2t, mv.x, vv.x);
                    pn.y = adam_step(pv.y, bo.y + acc[mt][j][rr * 2 + 1], b1t, b2t, mv.y, vv.y);
                    *reinterpret_cast<float2*>(&g_mo[idx]) = mv;
                    *reinterpret_cast<float2*>(&g_vo[idx]) = vv;
                    *reinterpret_cast<float2*>(&o_new[idx]) = pn;
                }
    } else {
        // -------- h update: D = rho(o_old) @ W2h (K=128, 2 chunks); term = A + D ----
        const int idx0 = bid - 128;
        const int bm0 = (idx0 >> 2) * 128, ntile = idx0 & 3;
        size_t wo = (size_t)ntile * 2 * 8192;
        mainloop(sm, smb, o_old, OUTPUT, bm0, g_W2h_h + wo, g_W2h_m + wo, g_W2h_l + wo,
                 2, tid, acc);
#pragma unroll
        for (int mt = 0; mt < 2; ++mt)
#pragma unroll
            for (int j = 0; j < 4; ++j)
#pragma unroll
                for (int rr = 0; rr < 2; ++rr) {
                    int r = bm0 + wm * 32 + mt * 16 + rr * 8 + (lane >> 2);
                    int col = ntile * 128 + wn * 32 + j * 8 + (lane & 3) * 2;
                    size_t idx = (size_t)r * HIDDEN + col;
                    float2 av = *reinterpret_cast<const float2*>(&g_A[idx]);
                    float2 pv = *reinterpret_cast<const float2*>(&h_old[idx]);
                    float2 mv = *reinterpret_cast<const float2*>(&g_mh[idx]);
                    float2 vv = *reinterpret_cast<const float2*>(&g_vh[idx]);
                    float2 pn;
                    pn.x = adam_step(pv.x, av.x + acc[mt][j][rr * 2],     b1t, b2t, mv.x, vv.x);
                    pn.y = adam_step(pv.y, av.y + acc[mt][j][rr * 2 + 1], b1t, b2t, mv.y, vv.y);
                    *reinterpret_cast<float2*>(&g_mh[idx]) = mv;
                    *reinterpret_cast<float2*>(&g_vh[idx]) = vv;
                    *reinterpret_cast<float2*>(&h_new[idx]) = pn;
                }
    }
}

// ---------------- prep kernels ----------------
__global__ void init_zero_kernel() {
    int i = blockIdx.x * blockDim.x + threadIdx.x;
    const int NH4 = BATCH * HIDDEN / 4, NO4 = BATCH * OUTPUT / 4;
    float4 z = make_float4(0.f, 0.f, 0.f, 0.f);
    if (i < NH4) {
        reinterpret_cast<float4*>(g_h0)[i] = z;
        reinterpret_cast<float4*>(g_mh)[i] = z;
        reinterpret_cast<float4*>(g_vh)[i] = z;
    }
    if (i < NO4) {
        reinterpret_cast<float4*>(g_o0)[i] = z;
        reinterpret_cast<float4*>(g_mo)[i] = z;
        reinterpret_cast<float4*>(g_vo)[i] = z;
    }
}

__global__ void prep_weights(const float* __restrict__ W1, const float* __restrict__ W2) {
    int t = blockIdx.x * blockDim.x + threadIdx.x;   // 0 .. 262143
    float v;
    __nv_bfloat16 *ph, *pm, *pl;
    int tile, r, cl;
    if (t < 65536) {                    // W2h: B[n][k] = W2[n][k]
        tile = t >> 13; int e = t & 8191; r = e >> 6; cl = e & 63;
        int tn = tile >> 1, kc = tile & 1;
        v = W2[(size_t)(tn * 128 + r) * OUTPUT + kc * 64 + cl];
        ph = g_W2h_h; pm = g_W2h_m; pl = g_W2h_l;
    } else if (t < 131072) {            // W2o: B[n][k] = W2[k][n]
        int t2 = t - 65536;
        tile = t2 >> 13; int e = t2 & 8191; r = e >> 6; cl = e & 63;
        v = W2[(size_t)(tile * 64 + cl) * OUTPUT + r];
        ph = g_W2o_h; pm = g_W2o_m; pl = g_W2o_l;
    } else {                            // W1T: B[n][k] = W1[k][n]
        int t3 = t - 131072;
        tile = t3 >> 13; int e = t3 & 8191; r = e >> 6; cl = e & 63;
        int tn = tile >> 2, kc = tile & 3;
        v = W1[(size_t)(kc * 64 + cl) * HIDDEN + tn * 128 + r];
        ph = g_W1T_h; pm = g_W1T_m; pl = g_W1T_l;
    }
    __nv_bfloat16 h = __float2bfloat16_rn(v);
    float r1 = v - __bfloat162float(h);
    __nv_bfloat16 m = __float2bfloat16_rn(r1);
    __nv_bfloat16 l = __float2bfloat16_rn(r1 - __bfloat162float(m));
    uint32_t off = swz(r, cl);
    size_t tb = (size_t)tile * 16384;
    *reinterpret_cast<__nv_bfloat16*>(reinterpret_cast<char*>(ph) + tb + off) = h;
    *reinterpret_cast<__nv_bfloat16*>(reinterpret_cast<char*>(pm) + tb + off) = m;
    *reinterpret_cast<__nv_bfloat16*>(reinterpret_cast<char*>(pl) + tb + off) = l;
}

// ---------------- launch ----------------
extern "C" void kernel_launch(void* const* d_in, const int* in_sizes, int n_in,
                              void* d_out, int out_size) {
    (void)in_sizes; (void)n_in; (void)out_size;
    const float* x   = (const float*)d_in[0];
    const float* W1  = (const float*)d_in[1];
    const float* W2  = (const float*)d_in[2];
    const float* b_h = (const float*)d_in[4];
    const float* b_o = (const float*)d_in[5];

    cudaFuncSetAttribute(pre_kernel,  cudaFuncAttributeMaxDynamicSharedMemorySize, SMEM_TOTAL);
    cudaFuncSetAttribute(step_kernel, cudaFuncAttributeMaxDynamicSharedMemorySize, SMEM_TOTAL);

    float *h0, *h1, *o0;
    cudaGetSymbolAddress((void**)&h0, g_h0);
    cudaGetSymbolAddress((void**)&h1, g_h1);
    cudaGetSymbolAddress((void**)&o0, g_o0);

    init_zero_kernel<<<(BATCH * HIDDEN / 4 + 255) / 256, 256>>>();
    prep_weights<<<262144 / 256, 256>>>(W1, W2);
    pre_kernel<<<512, 512, SMEM_TOTAL>>>(x, b_h);

    float* hbuf[2] = {h0, h1};
    float* obuf[2] = {o0, (float*)d_out};   // t odd writes obuf[1]; t=15 -> d_out

    for (int t = 1; t <= NITER; ++t) {
        int p = (t - 1) & 1;
        float b1t = 1.0f - powf(0.9f,   (float)t);
        float b2t = 1.0f - powf(0.999f, (float)t);
        step_kernel<<<640, 512, SMEM_TOTAL>>>(hbuf[p], obuf[p], hbuf[1 - p], obuf[1 - p],
                                              b_o, b1t, b2t);
    }
}

// round 5
// speedup vs baseline: 1.3883x; 1.0682x over previous
#include <cuda_runtime.h>
#include <cuda_bf16.h>
#include <math.h>
#include <stdint.h>

#define BATCH  16384
#define INPUT  256
#define HIDDEN 512
#define OUTPUT 128
#define NITER  15

// ---------------- device scratch ----------------
__device__ float g_A [BATCH * HIDDEN];
__device__ float g_h0[BATCH * HIDDEN];
__device__ float g_h1[BATCH * HIDDEN];
__device__ float g_mh[BATCH * HIDDEN];
__device__ float g_vh[BATCH * HIDDEN];
__device__ float g_o0[BATCH * OUTPUT];
__device__ float g_mo[BATCH * OUTPUT];
__device__ float g_vo[BATCH * OUTPUT];

// 3-way-split bf16 weight tiles (hi/mid/lo). Tile = 128 n-rows x 64 k-cols,
// pre-swizzled (XOR-128 on 128B rows) so kernel loads are straight 16B copies.
__device__ __nv_bfloat16 g_W2h_h[8  * 8192], g_W2h_m[8  * 8192], g_W2h_l[8  * 8192];
__device__ __nv_bfloat16 g_W2o_h[8  * 8192], g_W2o_m[8  * 8192], g_W2o_l[8  * 8192];
__device__ __nv_bfloat16 g_W1T_h[16 * 8192], g_W1T_m[16 * 8192], g_W1T_l[16 * 8192];

// ---------------- PTX helpers ----------------
__device__ __forceinline__ uint32_t smem_u32(const void* p) {
    uint32_t a;
    asm("{ .reg .u64 t; cvta.to.shared.u64 t, %1; cvt.u32.u64 %0, t; }" : "=r"(a) : "l"(p));
    return a;
}
__device__ __forceinline__ void ldsm4(uint32_t* r, uint32_t a) {
    asm volatile("ldmatrix.sync.aligned.m8n8.x4.shared.b16 {%0,%1,%2,%3}, [%4];"
                 : "=r"(r[0]), "=r"(r[1]), "=r"(r[2]), "=r"(r[3]) : "r"(a));
}
__device__ __forceinline__ void mma_bf16(float* c, const uint32_t* a, const uint32_t* b) {
    asm volatile("mma.sync.aligned.m16n8k16.row.col.f32.bf16.bf16.f32 "
                 "{%0,%1,%2,%3}, {%4,%5,%6,%7}, {%8,%9}, {%0,%1,%2,%3};"
                 : "+f"(c[0]), "+f"(c[1]), "+f"(c[2]), "+f"(c[3])
                 : "r"(a[0]), "r"(a[1]), "r"(a[2]), "r"(a[3]), "r"(b[0]), "r"(b[1]));
}
#define CP_ASYNC16(dst, src) asm volatile("cp.async.cg.shared.global [%0], [%1], 16;" :: "r"(dst), "l"(src) : "memory")
#define CP_COMMIT()          asm volatile("cp.async.commit_group;" ::: "memory")
#define CP_WAIT0()           asm volatile("cp.async.wait_group 0;" ::: "memory")

// ---------------- tile layout: 128 rows x 64 bf16 cols, 128B rows, XOR swizzle ----
__device__ __forceinline__ uint32_t swz(int r, int c) {   // c in bf16 elems
    uint32_t off = (uint32_t)((r >> 3) * 1024 + (r & 7) * 128 + c * 2);
    return off ^ ((off >> 3) & 0x70);
}

// smem: DOUBLE-buffered A (hi,mid,lo) and B (hi,mid,lo)
#define SM_A(bf, v)  ((bf) * 49152 + (v) * 16384)
#define SM_B(bf, v)  (98304 + (bf) * 49152 + (v) * 16384)
#define SMEM_TOTAL   196608

// ---------------- math ----------------
__device__ __forceinline__ float drho(float s) {
    return (s > 0.f && s < 1.f) ? 1.f : ((s == 0.f || s == 1.f) ? 0.5f : 0.f);
}
__device__ __forceinline__ float adam_step(float pv, float term, float b1t, float b2t,
                                           float& mio, float& vio) {
    float g  = pv - drho(pv) * term;
    float mn = 0.9f   * mio + 0.1f   * g;
    float vn = 0.999f * vio + 0.001f * (g * g);
    mio = mn; vio = vn;
    return pv - 0.01f * ((mn / b1t) / (sqrtf(vn / b2t) + 1e-8f));
}
__device__ __forceinline__ uint32_t pack2(__nv_bfloat16 a, __nv_bfloat16 b) {
    return ((uint32_t)__bfloat16_as_ushort(b) << 16) | __bfloat16_as_ushort(a);
}
// 3-way bf16 split of saturated float4
__device__ __forceinline__ void split3(float4 v, uint2& H, uint2& M, uint2& L) {
    float s[4] = {__saturatef(v.x), __saturatef(v.y), __saturatef(v.z), __saturatef(v.w)};
    __nv_bfloat16 h[4], m[4], l[4];
#pragma unroll
    for (int i = 0; i < 4; i++) {
        h[i] = __float2bfloat16_rn(s[i]);
        float r1 = s[i] - __bfloat162float(h[i]);
        m[i] = __float2bfloat16_rn(r1);
        float r2 = r1 - __bfloat162float(m[i]);
        l[i] = __float2bfloat16_rn(r2);
    }
    H.x = pack2(h[0], h[1]); H.y = pack2(h[2], h[3]);
    M.x = pack2(m[0], m[1]); M.y = pack2(m[2], m[3]);
    L.x = pack2(l[0], l[1]); L.y = pack2(l[2], l[3]);
}

// ---------------- mainloop: acc += rho(state)[128xK] @ B[Kx128] (6-product) ------
// 512 threads, 16 warps; warp tile 32(m) x 32(n). Double-buffered A and B:
// exactly ONE __syncthreads per chunk; next-chunk B cp.async + state LDGs issued
// before the mma block, split+STS into the idle buffer after it (no barrier).
__device__ __forceinline__ void mainloop(char* sm, uint32_t smb,
                                         const float* __restrict__ state, int sstride, int bm0,
                                         const __nv_bfloat16* __restrict__ wH,
                                         const __nv_bfloat16* __restrict__ wM,
                                         const __nv_bfloat16* __restrict__ wL,
                                         int nchunks, int tid, float acc[2][4][4]) {
    const int lane = tid & 31, wid = tid >> 5, wm = wid & 3, wn = wid >> 2;

    // stage chunk 0 into buffer 0
    {
#pragma unroll
        for (int i = 0; i < 4; i++) {
            int idx = tid + i * 512, r = idx >> 4, c4 = idx & 15;
            float4 v = *reinterpret_cast<const float4*>(
                &state[(size_t)(bm0 + r) * sstride + c4 * 4]);
            uint2 H, M, L; split3(v, H, M, L);
            uint32_t off = swz(r, c4 * 4);
            *reinterpret_cast<uint2*>(sm + SM_A(0, 0) + off) = H;
            *reinterpret_cast<uint2*>(sm + SM_A(0, 1) + off) = M;
            *reinterpret_cast<uint2*>(sm + SM_A(0, 2) + off) = L;
        }
#pragma unroll
        for (int i = 0; i < 2; i++) {
            int e = tid + i * 512;
            CP_ASYNC16(smb + SM_B(0, 0) + e * 16, wH + e * 8);
            CP_ASYNC16(smb + SM_B(0, 1) + e * 16, wM + e * 8);
            CP_ASYNC16(smb + SM_B(0, 2) + e * 16, wL + e * 8);
        }
        CP_COMMIT();
    }

    for (int c = 0; c < nchunks; ++c) {
        const int p = c & 1;
        CP_WAIT0();
        __syncthreads();                       // buf p fully staged (B arrived, A stores visible)
        const bool more = (c + 1 < nchunks);
        float4 v[4];
        if (more) {
            // next-chunk B copy into idle buffer + state LDGs, all before the mma block
            int bb = p ^ 1;
            size_t wo = (size_t)(c + 1) * 8192;
#pragma unroll
            for (int i = 0; i < 2; i++) {
                int e = tid + i * 512;
                CP_ASYNC16(smb + SM_B(bb, 0) + e * 16, wH + wo + e * 8);
                CP_ASYNC16(smb + SM_B(bb, 1) + e * 16, wM + wo + e * 8);
                CP_ASYNC16(smb + SM_B(bb, 2) + e * 16, wL + wo + e * 8);
            }
            CP_COMMIT();
            int kc0 = (c + 1) * 64;
#pragma unroll
            for (int i = 0; i < 4; i++) {
                int idx = tid + i * 512, r = idx >> 4, c4 = idx & 15;
                v[i] = *reinterpret_cast<const float4*>(
                    &state[(size_t)(bm0 + r) * sstride + kc0 + c4 * 4]);
            }
        }

        // -------- mma over chunk c (K=64, 4 k16 steps), 6 products --------
#pragma unroll
        for (int ks = 0; ks < 4; ++ks) {
            uint32_t A[3][2][4], B[3][2][4];
            int ac = ks * 16 + (lane >> 4) * 8;
#pragma unroll
            for (int mt = 0; mt < 2; ++mt) {
                uint32_t o = swz(wm * 32 + mt * 16 + (lane & 15), ac);
                ldsm4(A[0][mt], smb + SM_A(p, 0) + o);
                ldsm4(A[1][mt], smb + SM_A(p, 1) + o);
                ldsm4(A[2][mt], smb + SM_A(p, 2) + o);
            }
            int bc = ks * 16 + ((lane >> 3) & 1) * 8;
            int br = wn * 32 + ((lane >> 4) & 1) * 8 + (lane & 7);
#pragma unroll
            for (int bt = 0; bt < 2; ++bt) {
                uint32_t o = swz(br + bt * 16, bc);
                ldsm4(B[0][bt], smb + SM_B(p, 0) + o);
                ldsm4(B[1][bt], smb + SM_B(p, 1) + o);
                ldsm4(B[2][bt], smb + SM_B(p, 2) + o);
            }
#pragma unroll
            for (int mt = 0; mt < 2; ++mt)
#pragma unroll
                for (int bt = 0; bt < 2; ++bt) {
                    float* c0 = acc[mt][bt * 2];
                    float* c1 = acc[mt][bt * 2 + 1];
                    mma_bf16(c0, A[0][mt], &B[0][bt][0]);  // hh
                    mma_bf16(c1, A[0][mt], &B[0][bt][2]);
                    mma_bf16(c0, A[0][mt], &B[1][bt][0]);  // hm
                    mma_bf16(c1, A[0][mt], &B[1][bt][2]);
                    mma_bf16(c0, A[1][mt], &B[0][bt][0]);  // mh
                    mma_bf16(c1, A[1][mt], &B[0][bt][2]);
                    mma_bf16(c0, A[0][mt], &B[2][bt][0]);  // hl
                    mma_bf16(c1, A[0][mt], &B[2][bt][2]);
                    mma_bf16(c0, A[2][mt], &B[0][bt][0]);  // lh
                    mma_bf16(c1, A[2][mt], &B[0][bt][2]);
                    mma_bf16(c0, A[1][mt], &B[1][bt][0]);  // mm
                    mma_bf16(c1, A[1][mt], &B[1][bt][2]);
                }
        }
        if (more) {
            // split + store into the idle A buffer; next loop-top barrier publishes it
            int bb = p ^ 1;
#pragma unroll
            for (int i = 0; i < 4; i++) {
                int idx = tid + i * 512, r = idx >> 4, c4 = idx & 15;
                uint2 H, M, L; split3(v[i], H, M, L);
                uint32_t off = swz(r, c4 * 4);
                *reinterpret_cast<uint2*>(sm + SM_A(bb, 0) + off) = H;
                *reinterpret_cast<uint2*>(sm + SM_A(bb, 1) + off) = M;
                *reinterpret_cast<uint2*>(sm + SM_A(bb, 2) + off) = L;
            }
        }
    }
}

// ---------------- kernels ----------------
__global__ __launch_bounds__(512, 1)
void pre_kernel(const float* __restrict__ x, const float* __restrict__ b_h) {
    extern __shared__ __align__(128) char sm[];
    uint32_t smb = smem_u32(sm);
    const int tid = threadIdx.x, lane = tid & 31, wid = tid >> 5;
    const int wm = wid & 3, wn = wid >> 2;
    const int bid = blockIdx.x;
    const int bm0 = (bid >> 2) * 128, ntile = bid & 3;

    float acc[2][4][4];
#pragma unroll
    for (int a = 0; a < 2; a++)
#pragma unroll
        for (int b = 0; b < 4; b++)
#pragma unroll
            for (int q = 0; q < 4; q++) acc[a][b][q] = 0.f;

    size_t wo = (size_t)ntile * 4 * 8192;
    mainloop(sm, smb, x, INPUT, bm0, g_W1T_h + wo, g_W1T_m + wo, g_W1T_l + wo, 4, tid, acc);

#pragma unroll
    for (int mt = 0; mt < 2; ++mt)
#pragma unroll
        for (int j = 0; j < 4; ++j)
#pragma unroll
            for (int rr = 0; rr < 2; ++rr) {
                int r = bm0 + wm * 32 + mt * 16 + rr * 8 + (lane >> 2);
                int col = ntile * 128 + wn * 32 + j * 8 + (lane & 3) * 2;
                float2 bh = *reinterpret_cast<const float2*>(&b_h[col]);
                float2 out;
                out.x = acc[mt][j][rr * 2]     + bh.x;
                out.y = acc[mt][j][rr * 2 + 1] + bh.y;
                *reinterpret_cast<float2*>(&g_A[(size_t)r * HIDDEN + col]) = out;
            }
}

__global__ __launch_bounds__(512, 1)
void step_kernel(const float* __restrict__ h_old, const float* __restrict__ o_old,
                 float* __restrict__ h_new, float* __restrict__ o_new,
                 const float* __restrict__ b_o, float b1t, float b2t) {
    extern __shared__ __align__(128) char sm[];
    uint32_t smb = smem_u32(sm);
    const int tid = threadIdx.x, lane = tid & 31, wid = tid >> 5;
    const int wm = wid & 3, wn = wid >> 2;
    const int bid = blockIdx.x;

    float acc[2][4][4];
#pragma unroll
    for (int a = 0; a < 2; a++)
#pragma unroll
        for (int b = 0; b < 4; b++)
#pragma unroll
            for (int q = 0; q < 4; q++) acc[a][b][q] = 0.f;

    if (bid < 128) {
        // -------- o update: D = rho(h_old) @ W2o (K=512, 8 chunks) --------
        const int bm0 = bid * 128;
        mainloop(sm, smb, h_old, HIDDEN, bm0, g_W2o_h, g_W2o_m, g_W2o_l, 8, tid, acc);
#pragma unroll
        for (int mt = 0; mt < 2; ++mt)
#pragma unroll
            for (int j = 0; j < 4; ++j)
#pragma unroll
                for (int rr = 0; rr < 2; ++rr) {
                    int r = bm0 + wm * 32 + mt * 16 + rr * 8 + (lane >> 2);
                    int cc = wn * 32 + j * 8 + (lane & 3) * 2;
                    size_t idx = (size_t)r * OUTPUT + cc;
                    float2 bo = *reinterpret_cast<const float2*>(&b_o[cc]);
                    float2 pv = *reinterpret_cast<const float2*>(&o_old[idx]);
                    float2 mv = *reinterpret_cast<const float2*>(&g_mo[idx]);
                    float2 vv = *reinterpret_cast<const float2*>(&g_vo[idx]);
                    float2 pn;
                    pn.x = adam_step(pv.x, bo.x + acc[mt][j][rr * 2],     b1t, b2t, mv.x, vv.x);
                    pn.y = adam_step(pv.y, bo.y + acc[mt][j][rr * 2 + 1], b1t, b2t, mv.y, vv.y);
                    *reinterpret_cast<float2*>(&g_mo[idx]) = mv;
                    *reinterpret_cast<float2*>(&g_vo[idx]) = vv;
                    *reinterpret_cast<float2*>(&o_new[idx]) = pn;
                }
    } else {
        // -------- h update: D = rho(o_old) @ W2h (K=128, 2 chunks); term = A + D ----
        const int idx0 = bid - 128;
        const int bm0 = (idx0 >> 2) * 128, ntile = idx0 & 3;
        size_t wo = (size_t)ntile * 2 * 8192;
        mainloop(sm, smb, o_old, OUTPUT, bm0, g_W2h_h + wo, g_W2h_m + wo, g_W2h_l + wo,
                 2, tid, acc);
#pragma unroll
        for (int mt = 0; mt < 2; ++mt)
#pragma unroll
            for (int j = 0; j < 4; ++j)
#pragma unroll
                for (int rr = 0; rr < 2; ++rr) {
                    int r = bm0 + wm * 32 + mt * 16 + rr * 8 + (lane >> 2);
                    int col = ntile * 128 + wn * 32 + j * 8 + (lane & 3) * 2;
                    size_t idx = (size_t)r * HIDDEN + col;
                    float2 av = *reinterpret_cast<const float2*>(&g_A[idx]);
                    float2 pv = *reinterpret_cast<const float2*>(&h_old[idx]);
                    float2 mv = *reinterpret_cast<const float2*>(&g_mh[idx]);
                    float2 vv = *reinterpret_cast<const float2*>(&g_vh[idx]);
                    float2 pn;
                    pn.x = adam_step(pv.x, av.x + acc[mt][j][rr * 2],     b1t, b2t, mv.x, vv.x);
                    pn.y = adam_step(pv.y, av.y + acc[mt][j][rr * 2 + 1], b1t, b2t, mv.y, vv.y);
                    *reinterpret_cast<float2*>(&g_mh[idx]) = mv;
                    *reinterpret_cast<float2*>(&g_vh[idx]) = vv;
                    *reinterpret_cast<float2*>(&h_new[idx]) = pn;
                }
    }
}

// ---------------- prep kernels ----------------
__global__ void init_zero_kernel() {
    int i = blockIdx.x * blockDim.x + threadIdx.x;
    const int NH4 = BATCH * HIDDEN / 4, NO4 = BATCH * OUTPUT / 4;
    float4 z = make_float4(0.f, 0.f, 0.f, 0.f);
    if (i < NH4) {
        reinterpret_cast<float4*>(g_h0)[i] = z;
        reinterpret_cast<float4*>(g_mh)[i] = z;
        reinterpret_cast<float4*>(g_vh)[i] = z;
    }
    if (i < NO4) {
        reinterpret_cast<float4*>(g_o0)[i] = z;
        reinterpret_cast<float4*>(g_mo)[i] = z;
        reinterpret_cast<float4*>(g_vo)[i] = z;
    }
}

__global__ void prep_weights(const float* __restrict__ W1, const float* __restrict__ W2) {
    int t = blockIdx.x * blockDim.x + threadIdx.x;   // 0 .. 262143
    float v;
    __nv_bfloat16 *ph, *pm, *pl;
    int tile, r, cl;
    if (t < 65536) {                    // W2h: B[n][k] = W2[n][k]
        tile = t >> 13; int e = t & 8191; r = e >> 6; cl = e & 63;
        int tn = tile >> 1, kc = tile & 1;
        v = W2[(size_t)(tn * 128 + r) * OUTPUT + kc * 64 + cl];
        ph = g_W2h_h; pm = g_W2h_m; pl = g_W2h_l;
    } else if (t < 131072) {            // W2o: B[n][k] = W2[k][n]
        int t2 = t - 65536;
        tile = t2 >> 13; int e = t2 & 8191; r = e >> 6; cl = e & 63;
        v = W2[(size_t)(tile * 64 + cl) * OUTPUT + r];
        ph = g_W2o_h; pm = g_W2o_m; pl = g_W2o_l;
    } else {                            // W1T: B[n][k] = W1[k][n]
        int t3 = t - 131072;
        tile = t3 >> 13; int e = t3 & 8191; r = e >> 6; cl = e & 63;
        int tn = tile >> 2, kc = tile & 3;
        v = W1[(size_t)(kc * 64 + cl) * HIDDEN + tn * 128 + r];
        ph = g_W1T_h; pm = g_W1T_m; pl = g_W1T_l;
    }
    __nv_bfloat16 h = __float2bfloat16_rn(v);
    float r1 = v - __bfloat162float(h);
    __nv_bfloat16 m = __float2bfloat16_rn(r1);
    __nv_bfloat16 l = __float2bfloat16_rn(r1 - __bfloat162float(m));
    uint32_t off = swz(r, cl);
    size_t tb = (size_t)tile * 16384;
    *reinterpret_cast<__nv_bfloat16*>(reinterpret_cast<char*>(ph) + tb + off) = h;
    *reinterpret_cast<__nv_bfloat16*>(reinterpret_cast<char*>(pm) + tb + off) = m;
    *reinterpret_cast<__nv_bfloat16*>(reinterpret_cast<char*>(pl) + tb + off) = l;
}

// ---------------- launch ----------------
extern "C" void kernel_launch(void* const* d_in, const int* in_sizes, int n_in,
                              void* d_out, int out_size) {
    (void)in_sizes; (void)n_in; (void)out_size;
    const float* x   = (const float*)d_in[0];
    const float* W1  = (const float*)d_in[1];
    const float* W2  = (const float*)d_in[2];
    const float* b_h = (const float*)d_in[4];
    const float* b_o = (const float*)d_in[5];

    cudaFuncSetAttribute(pre_kernel,  cudaFuncAttributeMaxDynamicSharedMemorySize, SMEM_TOTAL);
    cudaFuncSetAttribute(step_kernel, cudaFuncAttributeMaxDynamicSharedMemorySize, SMEM_TOTAL);

    float *h0, *h1, *o0;
    cudaGetSymbolAddress((void**)&h0, g_h0);
    cudaGetSymbolAddress((void**)&h1, g_h1);
    cudaGetSymbolAddress((void**)&o0, g_o0);

    init_zero_kernel<<<(BATCH * HIDDEN / 4 + 255) / 256, 256>>>();
    prep_weights<<<262144 / 256, 256>>>(W1, W2);
    pre_kernel<<<512, 512, SMEM_TOTAL>>>(x, b_h);

    float* hbuf[2] = {h0, h1};
    float* obuf[2] = {o0, (float*)d_out};   // t odd writes obuf[1]; t=15 -> d_out

    for (int t = 1; t <= NITER; ++t) {
        int p = (t - 1) & 1;
        float b1t = 1.0f - powf(0.9f,   (float)t);
        float b2t = 1.0f - powf(0.999f, (float)t);
        step_kernel<<<640, 512, SMEM_TOTAL>>>(hbuf[p], obuf[p], hbuf[1 - p], obuf[1 - p],
                                              b_o, b1t, b2t);
    }
}

// round 6
// speedup vs baseline: 1.7411x; 1.2541x over previous
#include <cuda_runtime.h>
#include <cuda_fp16.h>
#include <math.h>
#include <stdint.h>

#define BATCH  16384
#define INPUT  256
#define HIDDEN 512
#define OUTPUT 128
#define NITER  15

// ---------------- device scratch ----------------
__device__ float g_A [BATCH * HIDDEN];
__device__ float g_h0[BATCH * HIDDEN];
__device__ float g_h1[BATCH * HIDDEN];
__device__ float g_mh[BATCH * HIDDEN];
__device__ float g_vh[BATCH * HIDDEN];
__device__ float g_o0[BATCH * OUTPUT];
__device__ float g_mo[BATCH * OUTPUT];
__device__ float g_vo[BATCH * OUTPUT];

// 2-way-split fp16 weight tiles (hi/lo). Tile = 128 n-rows x 64 k-cols,
// pre-swizzled (XOR-128 on 128B rows) so kernel loads are straight 16B copies.
__device__ __half g_W2h_h[8  * 8192], g_W2h_l[8  * 8192];
__device__ __half g_W2o_h[8  * 8192], g_W2o_l[8  * 8192];
__device__ __half g_W1T_h[16 * 8192], g_W1T_l[16 * 8192];

// ---------------- PTX helpers ----------------
__device__ __forceinline__ uint32_t smem_u32(const void* p) {
    uint32_t a;
    asm("{ .reg .u64 t; cvta.to.shared.u64 t, %1; cvt.u32.u64 %0, t; }" : "=r"(a) : "l"(p));
    return a;
}
__device__ __forceinline__ void ldsm4(uint32_t* r, uint32_t a) {
    asm volatile("ldmatrix.sync.aligned.m8n8.x4.shared.b16 {%0,%1,%2,%3}, [%4];"
                 : "=r"(r[0]), "=r"(r[1]), "=r"(r[2]), "=r"(r[3]) : "r"(a));
}
__device__ __forceinline__ void mma_f16(float* c, const uint32_t* a, const uint32_t* b) {
    asm volatile("mma.sync.aligned.m16n8k16.row.col.f32.f16.f16.f32 "
                 "{%0,%1,%2,%3}, {%4,%5,%6,%7}, {%8,%9}, {%0,%1,%2,%3};"
                 : "+f"(c[0]), "+f"(c[1]), "+f"(c[2]), "+f"(c[3])
                 : "r"(a[0]), "r"(a[1]), "r"(a[2]), "r"(a[3]), "r"(b[0]), "r"(b[1]));
}
#define CP_ASYNC16(dst, src) asm volatile("cp.async.cg.shared.global [%0], [%1], 16;" :: "r"(dst), "l"(src) : "memory")
#define CP_COMMIT()          asm volatile("cp.async.commit_group;" ::: "memory")
#define CP_WAIT0()           asm volatile("cp.async.wait_group 0;" ::: "memory")

// ---------------- tile layout: 128 rows x 64 fp16 cols, 128B rows, XOR swizzle ----
__device__ __forceinline__ uint32_t swz(int r, int c) {   // c in fp16 elems
    uint32_t off = (uint32_t)((r >> 3) * 1024 + (r & 7) * 128 + c * 2);
    return off ^ ((off >> 3) & 0x70);
}

// smem: DOUBLE-buffered A (hi,lo) and B (hi,lo)
#define SM_A(bf, v)  ((bf) * 32768 + (v) * 16384)
#define SM_B(bf, v)  (65536 + (bf) * 32768 + (v) * 16384)
#define SMEM_TOTAL   131072

// ---------------- math ----------------
__device__ __forceinline__ float drho(float s) {
    return (s > 0.f && s < 1.f) ? 1.f : ((s == 0.f || s == 1.f) ? 0.5f : 0.f);
}
__device__ __forceinline__ float adam_step(float pv, float term, float b1t, float b2t,
                                           float& mio, float& vio) {
    float g  = pv - drho(pv) * term;
    float mn = 0.9f   * mio + 0.1f   * g;
    float vn = 0.999f * vio + 0.001f * (g * g);
    mio = mn; vio = vn;
    return pv - 0.01f * ((mn / b1t) / (sqrtf(vn / b2t) + 1e-8f));
}
__device__ __forceinline__ uint32_t pack2h(__half a, __half b) {
    return ((uint32_t)__half_as_ushort(b) << 16) | __half_as_ushort(a);
}
// 2-way fp16 split of saturated float4
__device__ __forceinline__ void split2(float4 v, uint2& H, uint2& L) {
    float s[4] = {__saturatef(v.x), __saturatef(v.y), __saturatef(v.z), __saturatef(v.w)};
    __half h[4], l[4];
#pragma unroll
    for (int i = 0; i < 4; i++) {
        h[i] = __float2half_rn(s[i]);
        l[i] = __float2half_rn(s[i] - __half2float(h[i]));
    }
    H.x = pack2h(h[0], h[1]); H.y = pack2h(h[2], h[3]);
    L.x = pack2h(l[0], l[1]); L.y = pack2h(l[2], l[3]);
}

// ---------------- mainloop: acc += rho(state)[128xK] @ B[Kx128] (3-product fp16) ----
// 512 threads, 16 warps; warp tile 32(m) x 32(n). Double-buffered A and B:
// one __syncthreads per chunk; next-chunk B cp.async + state LDGs issued before
// the mma block, split+STS into the idle buffer after it (no second barrier).
__device__ __forceinline__ void mainloop(char* sm, uint32_t smb,
                                         const float* __restrict__ state, int sstride, int bm0,
                                         const __half* __restrict__ wH,
                                         const __half* __restrict__ wL,
                                         int nchunks, int tid, float acc[2][4][4]) {
    const int lane = tid & 31, wid = tid >> 5, wm = wid & 3, wn = wid >> 2;

    // stage chunk 0 into buffer 0
    {
#pragma unroll
        for (int i = 0; i < 4; i++) {
            int idx = tid + i * 512, r = idx >> 4, c4 = idx & 15;
            float4 v = *reinterpret_cast<const float4*>(
                &state[(size_t)(bm0 + r) * sstride + c4 * 4]);
            uint2 H, L; split2(v, H, L);
            uint32_t off = swz(r, c4 * 4);
            *reinterpret_cast<uint2*>(sm + SM_A(0, 0) + off) = H;
            *reinterpret_cast<uint2*>(sm + SM_A(0, 1) + off) = L;
        }
#pragma unroll
        for (int i = 0; i < 2; i++) {
            int e = tid + i * 512;
            CP_ASYNC16(smb + SM_B(0, 0) + e * 16, wH + e * 8);
            CP_ASYNC16(smb + SM_B(0, 1) + e * 16, wL + e * 8);
        }
        CP_COMMIT();
    }

    for (int c = 0; c < nchunks; ++c) {
        const int p = c & 1;
        CP_WAIT0();
        __syncthreads();                       // buf p fully staged
        const bool more = (c + 1 < nchunks);
        float4 v[4];
        if (more) {
            int bb = p ^ 1;
            size_t wo = (size_t)(c + 1) * 8192;
#pragma unroll
            for (int i = 0; i < 2; i++) {
                int e = tid + i * 512;
                CP_ASYNC16(smb + SM_B(bb, 0) + e * 16, wH + wo + e * 8);
                CP_ASYNC16(smb + SM_B(bb, 1) + e * 16, wL + wo + e * 8);
            }
            CP_COMMIT();
            int kc0 = (c + 1) * 64;
#pragma unroll
            for (int i = 0; i < 4; i++) {
                int idx = tid + i * 512, r = idx >> 4, c4 = idx & 15;
                v[i] = *reinterpret_cast<const float4*>(
                    &state[(size_t)(bm0 + r) * sstride + kc0 + c4 * 4]);
            }
        }

        // -------- mma over chunk c (K=64, 4 k16 steps), 3 products --------
#pragma unroll
        for (int ks = 0; ks < 4; ++ks) {
            uint32_t A[2][2][4], B[2][2][4];
            int ac = ks * 16 + (lane >> 4) * 8;
#pragma unroll
            for (int mt = 0; mt < 2; ++mt) {
                uint32_t o = swz(wm * 32 + mt * 16 + (lane & 15), ac);
                ldsm4(A[0][mt], smb + SM_A(p, 0) + o);
                ldsm4(A[1][mt], smb + SM_A(p, 1) + o);
            }
            int bc = ks * 16 + ((lane >> 3) & 1) * 8;
            int br = wn * 32 + ((lane >> 4) & 1) * 8 + (lane & 7);
#pragma unroll
            for (int bt = 0; bt < 2; ++bt) {
                uint32_t o = swz(br + bt * 16, bc);
                ldsm4(B[0][bt], smb + SM_B(p, 0) + o);
                ldsm4(B[1][bt], smb + SM_B(p, 1) + o);
            }
#pragma unroll
            for (int mt = 0; mt < 2; ++mt)
#pragma unroll
                for (int bt = 0; bt < 2; ++bt) {
                    float* c0 = acc[mt][bt * 2];
                    float* c1 = acc[mt][bt * 2 + 1];
                    mma_f16(c0, A[0][mt], &B[0][bt][0]);  // hh
                    mma_f16(c1, A[0][mt], &B[0][bt][2]);
                    mma_f16(c0, A[0][mt], &B[1][bt][0]);  // hl
                    mma_f16(c1, A[0][mt], &B[1][bt][2]);
                    mma_f16(c0, A[1][mt], &B[0][bt][0]);  // lh
                    mma_f16(c1, A[1][mt], &B[0][bt][2]);
                }
        }
        if (more) {
            int bb = p ^ 1;
#pragma unroll
            for (int i = 0; i < 4; i++) {
                int idx = tid + i * 512, r = idx >> 4, c4 = idx & 15;
                uint2 H, L; split2(v[i], H, L);
                uint32_t off = swz(r, c4 * 4);
                *reinterpret_cast<uint2*>(sm + SM_A(bb, 0) + off) = H;
                *reinterpret_cast<uint2*>(sm + SM_A(bb, 1) + off) = L;
            }
        }
    }
}

// ---------------- kernels ----------------
__global__ __launch_bounds__(512, 1)
void pre_kernel(const float* __restrict__ x, const float* __restrict__ b_h) {
    extern __shared__ __align__(128) char sm[];
    uint32_t smb = smem_u32(sm);
    const int tid = threadIdx.x, lane = tid & 31, wid = tid >> 5;
    const int wm = wid & 3, wn = wid >> 2;
    const int bid = blockIdx.x;
    const int bm0 = (bid >> 2) * 128, ntile = bid & 3;

    float acc[2][4][4];
#pragma unroll
    for (int a = 0; a < 2; a++)
#pragma unroll
        for (int b = 0; b < 4; b++)
#pragma unroll
            for (int q = 0; q < 4; q++) acc[a][b][q] = 0.f;

    size_t wo = (size_t)ntile * 4 * 8192;
    mainloop(sm, smb, x, INPUT, bm0, g_W1T_h + wo, g_W1T_l + wo, 4, tid, acc);

#pragma unroll
    for (int mt = 0; mt < 2; ++mt)
#pragma unroll
        for (int j = 0; j < 4; ++j)
#pragma unroll
            for (int rr = 0; rr < 2; ++rr) {
                int r = bm0 + wm * 32 + mt * 16 + rr * 8 + (lane >> 2);
                int col = ntile * 128 + wn * 32 + j * 8 + (lane & 3) * 2;
                float2 bh = *reinterpret_cast<const float2*>(&b_h[col]);
                float2 out;
                out.x = acc[mt][j][rr * 2]     + bh.x;
                out.y = acc[mt][j][rr * 2 + 1] + bh.y;
                *reinterpret_cast<float2*>(&g_A[(size_t)r * HIDDEN + col]) = out;
            }
}

__global__ __launch_bounds__(512, 1)
void step_kernel(const float* __restrict__ h_old, const float* __restrict__ o_old,
                 float* __restrict__ h_new, float* __restrict__ o_new,
                 const float* __restrict__ b_o, float b1t, float b2t) {
    extern __shared__ __align__(128) char sm[];
    uint32_t smb = smem_u32(sm);
    const int tid = threadIdx.x, lane = tid & 31, wid = tid >> 5;
    const int wm = wid & 3, wn = wid >> 2;
    const int bid = blockIdx.x;

    float acc[2][4][4];
#pragma unroll
    for (int a = 0; a < 2; a++)
#pragma unroll
        for (int b = 0; b < 4; b++)
#pragma unroll
            for (int q = 0; q < 4; q++) acc[a][b][q] = 0.f;

    if (bid < 128) {
        // -------- o update: D = rho(h_old) @ W2o (K=512, 8 chunks) --------
        const int bm0 = bid * 128;
        mainloop(sm, smb, h_old, HIDDEN, bm0, g_W2o_h, g_W2o_l, 8, tid, acc);
#pragma unroll
        for (int mt = 0; mt < 2; ++mt)
#pragma unroll
            for (int j = 0; j < 4; ++j)
#pragma unroll
                for (int rr = 0; rr < 2; ++rr) {
                    int r = bm0 + wm * 32 + mt * 16 + rr * 8 + (lane >> 2);
                    int cc = wn * 32 + j * 8 + (lane & 3) * 2;
                    size_t idx = (size_t)r * OUTPUT + cc;
                    float2 bo = *reinterpret_cast<const float2*>(&b_o[cc]);
                    float2 pv = *reinterpret_cast<const float2*>(&o_old[idx]);
                    float2 mv = *reinterpret_cast<const float2*>(&g_mo[idx]);
                    float2 vv = *reinterpret_cast<const float2*>(&g_vo[idx]);
                    float2 pn;
                    pn.x = adam_step(pv.x, bo.x + acc[mt][j][rr * 2],     b1t, b2t, mv.x, vv.x);
                    pn.y = adam_step(pv.y, bo.y + acc[mt][j][rr * 2 + 1], b1t, b2t, mv.y, vv.y);
                    *reinterpret_cast<float2*>(&g_mo[idx]) = mv;
                    *reinterpret_cast<float2*>(&g_vo[idx]) = vv;
                    *reinterpret_cast<float2*>(&o_new[idx]) = pn;
                }
    } else {
        // -------- h update: D = rho(o_old) @ W2h (K=128, 2 chunks); term = A + D ----
        const int idx0 = bid - 128;
        const int bm0 = (idx0 >> 2) * 128, ntile = idx0 & 3;
        size_t wo = (size_t)ntile * 2 * 8192;
        mainloop(sm, smb, o_old, OUTPUT, bm0, g_W2h_h + wo, g_W2h_l + wo, 2, tid, acc);
#pragma unroll
        for (int mt = 0; mt < 2; ++mt)
#pragma unroll
            for (int j = 0; j < 4; ++j)
#pragma unroll
                for (int rr = 0; rr < 2; ++rr) {
                    int r = bm0 + wm * 32 + mt * 16 + rr * 8 + (lane >> 2);
                    int col = ntile * 128 + wn * 32 + j * 8 + (lane & 3) * 2;
                    size_t idx = (size_t)r * HIDDEN + col;
                    float2 av = *reinterpret_cast<const float2*>(&g_A[idx]);
                    float2 pv = *reinterpret_cast<const float2*>(&h_old[idx]);
                    float2 mv = *reinterpret_cast<const float2*>(&g_mh[idx]);
                    float2 vv = *reinterpret_cast<const float2*>(&g_vh[idx]);
                    float2 pn;
                    pn.x = adam_step(pv.x, av.x + acc[mt][j][rr * 2],     b1t, b2t, mv.x, vv.x);
                    pn.y = adam_step(pv.y, av.y + acc[mt][j][rr * 2 + 1], b1t, b2t, mv.y, vv.y);
                    *reinterpret_cast<float2*>(&g_mh[idx]) = mv;
                    *reinterpret_cast<float2*>(&g_vh[idx]) = vv;
                    *reinterpret_cast<float2*>(&h_new[idx]) = pn;
                }
    }
}

// ---------------- prep kernels ----------------
__global__ void init_zero_kernel() {
    int i = blockIdx.x * blockDim.x + threadIdx.x;
    const int NH4 = BATCH * HIDDEN / 4, NO4 = BATCH * OUTPUT / 4;
    float4 z = make_float4(0.f, 0.f, 0.f, 0.f);
    if (i < NH4) {
        reinterpret_cast<float4*>(g_h0)[i] = z;
        reinterpret_cast<float4*>(g_mh)[i] = z;
        reinterpret_cast<float4*>(g_vh)[i] = z;
    }
    if (i < NO4) {
        reinterpret_cast<float4*>(g_o0)[i] = z;
        reinterpret_cast<float4*>(g_mo)[i] = z;
        reinterpret_cast<float4*>(g_vo)[i] = z;
    }
}

__global__ void prep_weights(const float* __restrict__ W1, const float* __restrict__ W2) {
    int t = blockIdx.x * blockDim.x + threadIdx.x;   // 0 .. 262143
    float v;
    __half *ph, *pl;
    int tile, r, cl;
    if (t < 65536) {                    // W2h: B[n][k] = W2[n][k]
        tile = t >> 13; int e = t & 8191; r = e >> 6; cl = e & 63;
        int tn = tile >> 1, kc = tile & 1;
        v = W2[(size_t)(tn * 128 + r) * OUTPUT + kc * 64 + cl];
        ph = g_W2h_h; pl = g_W2h_l;
    } else if (t < 131072) {            // W2o: B[n][k] = W2[k][n]
        int t2 = t - 65536;
        tile = t2 >> 13; int e = t2 & 8191; r = e >> 6; cl = e & 63;
        v = W2[(size_t)(tile * 64 + cl) * OUTPUT + r];
        ph = g_W2o_h; pl = g_W2o_l;
    } else {                            // W1T: B[n][k] = W1[k][n]
        int t3 = t - 131072;
        tile = t3 >> 13; int e = t3 & 8191; r = e >> 6; cl = e & 63;
        int tn = tile >> 2, kc = tile & 3;
        v = W1[(size_t)(kc * 64 + cl) * HIDDEN + tn * 128 + r];
        ph = g_W1T_h; pl = g_W1T_l;
    }
    __half h = __float2half_rn(v);
    __half l = __float2half_rn(v - __half2float(h));
    uint32_t off = swz(r, cl);
    size_t tb = (size_t)tile * 16384;
    *reinterpret_cast<__half*>(reinterpret_cast<char*>(ph) + tb + off) = h;
    *reinterpret_cast<__half*>(reinterpret_cast<char*>(pl) + tb + off) = l;
}

// ---------------- launch ----------------
extern "C" void kernel_launch(void* const* d_in, const int* in_sizes, int n_in,
                              void* d_out, int out_size) {
    (void)in_sizes; (void)n_in; (void)out_size;
    const float* x   = (const float*)d_in[0];
    const float* W1  = (const float*)d_in[1];
    const float* W2  = (const float*)d_in[2];
    const float* b_h = (const float*)d_in[4];
    const float* b_o = (const float*)d_in[5];

    cudaFuncSetAttribute(pre_kernel,  cudaFuncAttributeMaxDynamicSharedMemorySize, SMEM_TOTAL);
    cudaFuncSetAttribute(step_kernel, cudaFuncAttributeMaxDynamicSharedMemorySize, SMEM_TOTAL);

    float *h0, *h1, *o0;
    cudaGetSymbolAddress((void**)&h0, g_h0);
    cudaGetSymbolAddress((void**)&h1, g_h1);
    cudaGetSymbolAddress((void**)&o0, g_o0);

    init_zero_kernel<<<(BATCH * HIDDEN / 4 + 255) / 256, 256>>>();
    prep_weights<<<262144 / 256, 256>>>(W1, W2);
    pre_kernel<<<512, 512, SMEM_TOTAL>>>(x, b_h);

    float* hbuf[2] = {h0, h1};
    float* obuf[2] = {o0, (float*)d_out};   // t odd writes obuf[1]; t=15 -> d_out

    for (int t = 1; t <= NITER; ++t) {
        int p = (t - 1) & 1;
        float b1t = 1.0f - powf(0.9f,   (float)t);
        float b2t = 1.0f - powf(0.999f, (float)t);
        step_kernel<<<640, 512, SMEM_TOTAL>>>(hbuf[p], obuf[p], hbuf[1 - p], obuf[1 - p],
                                              b_o, b1t, b2t);
    }
}

// round 7
// speedup vs baseline: 1.8791x; 1.0793x over previous
#include <cuda_runtime.h>
#include <cuda_fp16.h>
#include <math.h>
#include <stdint.h>

#define BATCH  16384
#define INPUT  256
#define HIDDEN 512
#define OUTPUT 128
#define NITER  15

// ---------------- device scratch ----------------
__device__ float g_A [BATCH * HIDDEN];
__device__ float g_h0[BATCH * HIDDEN];
__device__ float g_h1[BATCH * HIDDEN];
__device__ float g_mh[BATCH * HIDDEN];
__device__ float g_vh[BATCH * HIDDEN];
__device__ float g_o0[BATCH * OUTPUT];
__device__ float g_mo[BATCH * OUTPUT];
__device__ float g_vo[BATCH * OUTPUT];

// 2-way-split fp16 weight tiles (hi/lo). Tile = 128 n-rows x 64 k-cols,
// pre-swizzled (XOR-128 on 128B rows) so kernel loads are straight 16B copies.
__device__ __half g_W2h_h[8  * 8192], g_W2h_l[8  * 8192];
__device__ __half g_W2o_h[8  * 8192], g_W2o_l[8  * 8192];
__device__ __half g_W1T_h[16 * 8192], g_W1T_l[16 * 8192];

// ---------------- PTX helpers ----------------
__device__ __forceinline__ uint32_t smem_u32(const void* p) {
    uint32_t a;
    asm("{ .reg .u64 t; cvta.to.shared.u64 t, %1; cvt.u32.u64 %0, t; }" : "=r"(a) : "l"(p));
    return a;
}
__device__ __forceinline__ void ldsm4(uint32_t* r, uint32_t a) {
    asm volatile("ldmatrix.sync.aligned.m8n8.x4.shared.b16 {%0,%1,%2,%3}, [%4];"
                 : "=r"(r[0]), "=r"(r[1]), "=r"(r[2]), "=r"(r[3]) : "r"(a));
}
__device__ __forceinline__ void mma_f16(float* c, const uint32_t* a, const uint32_t* b) {
    asm volatile("mma.sync.aligned.m16n8k16.row.col.f32.f16.f16.f32 "
                 "{%0,%1,%2,%3}, {%4,%5,%6,%7}, {%8,%9}, {%0,%1,%2,%3};"
                 : "+f"(c[0]), "+f"(c[1]), "+f"(c[2]), "+f"(c[3])
                 : "r"(a[0]), "r"(a[1]), "r"(a[2]), "r"(a[3]), "r"(b[0]), "r"(b[1]));
}
#define CP_ASYNC16(dst, src) asm volatile("cp.async.cg.shared.global [%0], [%1], 16;" :: "r"(dst), "l"(src) : "memory")
#define CP_COMMIT()          asm volatile("cp.async.commit_group;" ::: "memory")
#define CP_WAIT0()           asm volatile("cp.async.wait_group 0;" ::: "memory")
#define PREF_L2(p)           asm volatile("prefetch.global.L2 [%0];" :: "l"(p))

// ---------------- tile layout: 128B rows, XOR swizzle ----
__device__ __forceinline__ uint32_t swz(int r, int c) {   // c in fp16 elems
    uint32_t off = (uint32_t)((r >> 3) * 1024 + (r & 7) * 128 + c * 2);
    return off ^ ((off >> 3) & 0x70);
}

// smem per CTA (96KB -> 2 CTAs/SM): A double (hi,lo) 64-row tiles, B double (hi,lo) 128-row tiles
#define SM_A(bf, v)  ((bf) * 16384 + (v) * 8192)
#define SM_B(bf, v)  (32768 + (bf) * 32768 + (v) * 16384)
#define SMEM_TOTAL   98304

// ---------------- math ----------------
__device__ __forceinline__ float drho(float s) {
    return (s > 0.f && s < 1.f) ? 1.f : ((s == 0.f || s == 1.f) ? 0.5f : 0.f);
}
__device__ __forceinline__ float adam_step(float pv, float term, float b1t, float b2t,
                                           float& mio, float& vio) {
    float g  = pv - drho(pv) * term;
    float mn = 0.9f   * mio + 0.1f   * g;
    float vn = 0.999f * vio + 0.001f * (g * g);
    mio = mn; vio = vn;
    return pv - 0.01f * ((mn / b1t) / (sqrtf(vn / b2t) + 1e-8f));
}
__device__ __forceinline__ uint32_t pack2h(__half a, __half b) {
    return ((uint32_t)__half_as_ushort(b) << 16) | __half_as_ushort(a);
}
__device__ __forceinline__ void split2(float4 v, uint2& H, uint2& L) {
    float s[4] = {__saturatef(v.x), __saturatef(v.y), __saturatef(v.z), __saturatef(v.w)};
    __half h[4], l[4];
#pragma unroll
    for (int i = 0; i < 4; i++) {
        h[i] = __float2half_rn(s[i]);
        l[i] = __float2half_rn(s[i] - __half2float(h[i]));
    }
    H.x = pack2h(h[0], h[1]); H.y = pack2h(h[2], h[3]);
    L.x = pack2h(l[0], l[1]); L.y = pack2h(l[2], l[3]);
}

// ---------------- mainloop: acc += rho(state)[64xK] @ B[Kx128] (3-product fp16) ----
// 256 threads, 8 warps; warp tile 32(m) x 32(n): wm = wid&1, wn = wid>>1.
__device__ __forceinline__ void mainloop(char* sm, uint32_t smb,
                                         const float* __restrict__ state, int sstride, int bm0,
                                         const __half* __restrict__ wH,
                                         const __half* __restrict__ wL,
                                         int nchunks, int tid, float acc[2][4][4]) {
    const int lane = tid & 31, wid = tid >> 5, wm = wid & 1, wn = wid >> 1;

    // stage chunk 0 into buffer 0
    {
#pragma unroll
        for (int i = 0; i < 4; i++) {
            int idx = tid + i * 256, r = idx >> 4, c4 = idx & 15;
            float4 v = *reinterpret_cast<const float4*>(
                &state[(size_t)(bm0 + r) * sstride + c4 * 4]);
            uint2 H, L; split2(v, H, L);
            uint32_t off = swz(r, c4 * 4);
            *reinterpret_cast<uint2*>(sm + SM_A(0, 0) + off) = H;
            *reinterpret_cast<uint2*>(sm + SM_A(0, 1) + off) = L;
        }
#pragma unroll
        for (int i = 0; i < 4; i++) {
            int e = tid + i * 256;
            CP_ASYNC16(smb + SM_B(0, 0) + e * 16, wH + e * 8);
            CP_ASYNC16(smb + SM_B(0, 1) + e * 16, wL + e * 8);
        }
        CP_COMMIT();
    }

    for (int c = 0; c < nchunks; ++c) {
        const int p = c & 1;
        CP_WAIT0();
        __syncthreads();                       // buf p fully staged
        const bool more = (c + 1 < nchunks);
        float4 v[4];
        if (more) {
            int bb = p ^ 1;
            size_t wo = (size_t)(c + 1) * 8192;
#pragma unroll
            for (int i = 0; i < 4; i++) {
                int e = tid + i * 256;
                CP_ASYNC16(smb + SM_B(bb, 0) + e * 16, wH + wo + e * 8);
                CP_ASYNC16(smb + SM_B(bb, 1) + e * 16, wL + wo + e * 8);
            }
            CP_COMMIT();
            int kc0 = (c + 1) * 64;
#pragma unroll
            for (int i = 0; i < 4; i++) {
                int idx = tid + i * 256, r = idx >> 4, c4 = idx & 15;
                v[i] = *reinterpret_cast<const float4*>(
                    &state[(size_t)(bm0 + r) * sstride + kc0 + c4 * 4]);
            }
        }

        // -------- mma over chunk c (K=64, 4 k16 steps), 3 products --------
#pragma unroll
        for (int ks = 0; ks < 4; ++ks) {
            uint32_t A[2][2][4], B[2][2][4];
            int ac = ks * 16 + (lane >> 4) * 8;
#pragma unroll
            for (int mt = 0; mt < 2; ++mt) {
                uint32_t o = swz(wm * 32 + mt * 16 + (lane & 15), ac);
                ldsm4(A[0][mt], smb + SM_A(p, 0) + o);
                ldsm4(A[1][mt], smb + SM_A(p, 1) + o);
            }
            int bc = ks * 16 + ((lane >> 3) & 1) * 8;
            int br = wn * 32 + ((lane >> 4) & 1) * 8 + (lane & 7);
#pragma unroll
            for (int bt = 0; bt < 2; ++bt) {
                uint32_t o = swz(br + bt * 16, bc);
                ldsm4(B[0][bt], smb + SM_B(p, 0) + o);
                ldsm4(B[1][bt], smb + SM_B(p, 1) + o);
            }
#pragma unroll
            for (int mt = 0; mt < 2; ++mt)
#pragma unroll
                for (int bt = 0; bt < 2; ++bt) {
                    float* c0 = acc[mt][bt * 2];
                    float* c1 = acc[mt][bt * 2 + 1];
                    mma_f16(c0, A[0][mt], &B[0][bt][0]);  // hh
                    mma_f16(c1, A[0][mt], &B[0][bt][2]);
                    mma_f16(c0, A[0][mt], &B[1][bt][0]);  // hl
                    mma_f16(c1, A[0][mt], &B[1][bt][2]);
                    mma_f16(c0, A[1][mt], &B[0][bt][0]);  // lh
                    mma_f16(c1, A[1][mt], &B[0][bt][2]);
                }
        }
        if (more) {
            int bb = p ^ 1;
#pragma unroll
            for (int i = 0; i < 4; i++) {
                int idx = tid + i * 256, r = idx >> 4, c4 = idx & 15;
                uint2 H, L; split2(v[i], H, L);
                uint32_t off = swz(r, c4 * 4);
                *reinterpret_cast<uint2*>(sm + SM_A(bb, 0) + off) = H;
                *reinterpret_cast<uint2*>(sm + SM_A(bb, 1) + off) = L;
            }
        }
    }
}

// ---------------- kernels ----------------
__global__ __launch_bounds__(256, 2)
void pre_kernel(const float* __restrict__ x, const float* __restrict__ b_h) {
    extern __shared__ __align__(128) char sm[];
    uint32_t smb = smem_u32(sm);
    const int tid = threadIdx.x, lane = tid & 31, wid = tid >> 5;
    const int wm = wid & 1, wn = wid >> 1;
    const int bid = blockIdx.x;
    const int bm0 = (bid >> 2) * 64, ntile = bid & 3;

    float acc[2][4][4];
#pragma unroll
    for (int a = 0; a < 2; a++)
#pragma unroll
        for (int b = 0; b < 4; b++)
#pragma unroll
            for (int q = 0; q < 4; q++) acc[a][b][q] = 0.f;

    size_t wo = (size_t)ntile * 4 * 8192;
    mainloop(sm, smb, x, INPUT, bm0, g_W1T_h + wo, g_W1T_l + wo, 4, tid, acc);

#pragma unroll
    for (int mt = 0; mt < 2; ++mt)
#pragma unroll
        for (int j = 0; j < 4; ++j)
#pragma unroll
            for (int rr = 0; rr < 2; ++rr) {
                int r = bm0 + wm * 32 + mt * 16 + rr * 8 + (lane >> 2);
                int col = ntile * 128 + wn * 32 + j * 8 + (lane & 3) * 2;
                float2 bh = *reinterpret_cast<const float2*>(&b_h[col]);
                float2 out;
                out.x = acc[mt][j][rr * 2]     + bh.x;
                out.y = acc[mt][j][rr * 2 + 1] + bh.y;
                *reinterpret_cast<float2*>(&g_A[(size_t)r * HIDDEN + col]) = out;
            }
}

__global__ __launch_bounds__(256, 2)
void step_kernel(const float* __restrict__ h_old, const float* __restrict__ o_old,
                 float* __restrict__ h_new, float* __restrict__ o_new,
                 const float* __restrict__ b_o, float b1t, float b2t) {
    extern __shared__ __align__(128) char sm[];
    uint32_t smb = smem_u32(sm);
    const int tid = threadIdx.x, lane = tid & 31, wid = tid >> 5;
    const int wm = wid & 1, wn = wid >> 1;
    const int bid = blockIdx.x;

    float acc[2][4][4];
#pragma unroll
    for (int a = 0; a < 2; a++)
#pragma unroll
        for (int b = 0; b < 4; b++)
#pragma unroll
            for (int q = 0; q < 4; q++) acc[a][b][q] = 0.f;

    if (bid < 256) {
        // -------- o update: D = rho(h_old) @ W2o (K=512, 8 chunks) --------
        const int bm0 = bid * 64;
        // prefetch epilogue lines into L2 (1 x 128B line per thread per array)
        {
            size_t base = (size_t)bm0 * OUTPUT;
            const char* pa = (const char*)(o_old + base) + tid * 128;
            const char* pb = (const char*)(g_mo  + base) + tid * 128;
            const char* pc = (const char*)(g_vo  + base) + tid * 128;
            PREF_L2(pa); PREF_L2(pb); PREF_L2(pc);
        }
        mainloop(sm, smb, h_old, HIDDEN, bm0, g_W2o_h, g_W2o_l, 8, tid, acc);
#pragma unroll
        for (int mt = 0; mt < 2; ++mt)
#pragma unroll
            for (int j = 0; j < 4; ++j)
#pragma unroll
                for (int rr = 0; rr < 2; ++rr) {
                    int r = bm0 + wm * 32 + mt * 16 + rr * 8 + (lane >> 2);
                    int cc = wn * 32 + j * 8 + (lane & 3) * 2;
                    size_t idx = (size_t)r * OUTPUT + cc;
                    float2 bo = *reinterpret_cast<const float2*>(&b_o[cc]);
                    float2 pv = *reinterpret_cast<const float2*>(&o_old[idx]);
                    float2 mv = *reinterpret_cast<const float2*>(&g_mo[idx]);
                    float2 vv = *reinterpret_cast<const float2*>(&g_vo[idx]);
                    float2 pn;
                    pn.x = adam_step(pv.x, bo.x + acc[mt][j][rr * 2],     b1t, b2t, mv.x, vv.x);
                    pn.y = adam_step(pv.y, bo.y + acc[mt][j][rr * 2 + 1], b1t, b2t, mv.y, vv.y);
                    *reinterpret_cast<float2*>(&g_mo[idx]) = mv;
                    *reinterpret_cast<float2*>(&g_vo[idx]) = vv;
                    *reinterpret_cast<float2*>(&o_new[idx]) = pn;
                }
    } else {
        // -------- h update: D = rho(o_old) @ W2h (K=128, 2 chunks); term = A + D ----
        const int idx0 = bid - 256;
        const int bm0 = (idx0 >> 2) * 64, ntile = idx0 & 3;
        // prefetch epilogue lines (row tid>>2, 128B segment tid&3 of the 512B window)
        {
            int r = tid >> 2, cseg = (tid & 3) * 32;
            size_t off = (size_t)(bm0 + r) * HIDDEN + ntile * 128 + cseg;
            PREF_L2(g_A  + off); PREF_L2(h_old + off);
            PREF_L2(g_mh + off); PREF_L2(g_vh + off);
        }
        size_t wo = (size_t)ntile * 2 * 8192;
        mainloop(sm, smb, o_old, OUTPUT, bm0, g_W2h_h + wo, g_W2h_l + wo, 2, tid, acc);
#pragma unroll
        for (int mt = 0; mt < 2; ++mt)
#pragma unroll
            for (int j = 0; j < 4; ++j)
#pragma unroll
                for (int rr = 0; rr < 2; ++rr) {
                    int r = bm0 + wm * 32 + mt * 16 + rr * 8 + (lane >> 2);
                    int col = ntile * 128 + wn * 32 + j * 8 + (lane & 3) * 2;
                    size_t idx = (size_t)r * HIDDEN + col;
                    float2 av = *reinterpret_cast<const float2*>(&g_A[idx]);
                    float2 pv = *reinterpret_cast<const float2*>(&h_old[idx]);
                    float2 mv = *reinterpret_cast<const float2*>(&g_mh[idx]);
                    float2 vv = *reinterpret_cast<const float2*>(&g_vh[idx]);
                    float2 pn;
                    pn.x = adam_step(pv.x, av.x + acc[mt][j][rr * 2],     b1t, b2t, mv.x, vv.x);
                    pn.y = adam_step(pv.y, av.y + acc[mt][j][rr * 2 + 1], b1t, b2t, mv.y, vv.y);
                    *reinterpret_cast<float2*>(&g_mh[idx]) = mv;
                    *reinterpret_cast<float2*>(&g_vh[idx]) = vv;
                    *reinterpret_cast<float2*>(&h_new[idx]) = pn;
                }
    }
}

// ---------------- prep kernels ----------------
__global__ void init_zero_kernel() {
    int i = blockIdx.x * blockDim.x + threadIdx.x;
    const int NH4 = BATCH * HIDDEN / 4, NO4 = BATCH * OUTPUT / 4;
    float4 z = make_float4(0.f, 0.f, 0.f, 0.f);
    if (i < NH4) {
        reinterpret_cast<float4*>(g_h0)[i] = z;
        reinterpret_cast<float4*>(g_mh)[i] = z;
        reinterpret_cast<float4*>(g_vh)[i] = z;
    }
    if (i < NO4) {
        reinterpret_cast<float4*>(g_o0)[i] = z;
        reinterpret_cast<float4*>(g_mo)[i] = z;
        reinterpret_cast<float4*>(g_vo)[i] = z;
    }
}

__global__ void prep_weights(const float* __restrict__ W1, const float* __restrict__ W2) {
    int t = blockIdx.x * blockDim.x + threadIdx.x;   // 0 .. 262143
    float v;
    __half *ph, *pl;
    int tile, r, cl;
    if (t < 65536) {                    // W2h: B[n][k] = W2[n][k]
        tile = t >> 13; int e = t & 8191; r = e >> 6; cl = e & 63;
        int tn = tile >> 1, kc = tile & 1;
        v = W2[(size_t)(tn * 128 + r) * OUTPUT + kc * 64 + cl];
        ph = g_W2h_h; pl = g_W2h_l;
    } else if (t < 131072) {            // W2o: B[n][k] = W2[k][n]
        int t2 = t - 65536;
        tile = t2 >> 13; int e = t2 & 8191; r = e >> 6; cl = e & 63;
        v = W2[(size_t)(tile * 64 + cl) * OUTPUT + r];
        ph = g_W2o_h; pl = g_W2o_l;
    } else {                            // W1T: B[n][k] = W1[k][n]
        int t3 = t - 131072;
        tile = t3 >> 13; int e = t3 & 8191; r = e >> 6; cl = e & 63;
        int tn = tile >> 2, kc = tile & 3;
        v = W1[(size_t)(kc * 64 + cl) * HIDDEN + tn * 128 + r];
        ph = g_W1T_h; pl = g_W1T_l;
    }
    __half h = __float2half_rn(v);
    __half l = __float2half_rn(v - __half2float(h));
    uint32_t off = swz(r, cl);
    size_t tb = (size_t)tile * 16384;
    *reinterpret_cast<__half*>(reinterpret_cast<char*>(ph) + tb + off) = h;
    *reinterpret_cast<__half*>(reinterpret_cast<char*>(pl) + tb + off) = l;
}

// ---------------- launch ----------------
extern "C" void kernel_launch(void* const* d_in, const int* in_sizes, int n_in,
                              void* d_out, int out_size) {
    (void)in_sizes; (void)n_in; (void)out_size;
    const float* x   = (const float*)d_in[0];
    const float* W1  = (const float*)d_in[1];
    const float* W2  = (const float*)d_in[2];
    const float* b_h = (const float*)d_in[4];
    const float* b_o = (const float*)d_in[5];

    cudaFuncSetAttribute(pre_kernel,  cudaFuncAttributeMaxDynamicSharedMemorySize, SMEM_TOTAL);
    cudaFuncSetAttribute(step_kernel, cudaFuncAttributeMaxDynamicSharedMemorySize, SMEM_TOTAL);

    float *h0, *h1, *o0;
    cudaGetSymbolAddress((void**)&h0, g_h0);
    cudaGetSymbolAddress((void**)&h1, g_h1);
    cudaGetSymbolAddress((void**)&o0, g_o0);

    init_zero_kernel<<<(BATCH * HIDDEN / 4 + 255) / 256, 256>>>();
    prep_weights<<<262144 / 256, 256>>>(W1, W2);
    pre_kernel<<<1024, 256, SMEM_TOTAL>>>(x, b_h);

    float* hbuf[2] = {h0, h1};
    float* obuf[2] = {o0, (float*)d_out};   // t odd writes obuf[1]; t=15 -> d_out

    for (int t = 1; t <= NITER; ++t) {
        int p = (t - 1) & 1;
        float b1t = 1.0f - powf(0.9f,   (float)t);
        float b2t = 1.0f - powf(0.999f, (float)t);
        step_kernel<<<1280, 256, SMEM_TOTAL>>>(hbuf[p], obuf[p], hbuf[1 - p], obuf[1 - p],
                                               b_o, b1t, b2t);
    }
}

// round 8
// speedup vs baseline: 2.0242x; 1.0772x over previous
#include <cuda_runtime.h>
#include <cuda_fp16.h>
#include <math.h>
#include <stdint.h>

#define BATCH  16384
#define INPUT  256
#define HIDDEN 512
#define OUTPUT 128
#define NITER  15

// ---------------- device scratch ----------------
__device__ float g_A  [BATCH * HIDDEN];
__device__ float g_hr0[BATCH * HIDDEN], g_hr1[BATCH * HIDDEN];   // raw h (Adam pv)
__device__ float g_mh [BATCH * HIDDEN], g_vh [BATCH * HIDDEN];
__device__ float g_or0[BATCH * OUTPUT];                          // raw o buf0 (buf1 = d_out)
__device__ float g_mo [BATCH * OUTPUT], g_vo [BATCH * OUTPUT];
// rho-clipped fp16 hi/lo split state (GEMM operand form)
__device__ __half g_hch0[BATCH * HIDDEN], g_hcl0[BATCH * HIDDEN];
__device__ __half g_hch1[BATCH * HIDDEN], g_hcl1[BATCH * HIDDEN];
__device__ __half g_och0[BATCH * OUTPUT], g_ocl0[BATCH * OUTPUT];
__device__ __half g_och1[BATCH * OUTPUT], g_ocl1[BATCH * OUTPUT];
__device__ __half g_xch [BATCH * INPUT],  g_xcl [BATCH * INPUT];

// 2-way-split fp16 weight tiles (hi/lo). Tile = 128 n-rows x 64 k-cols, pre-swizzled.
__device__ __half g_W2h_h[8  * 8192], g_W2h_l[8  * 8192];
__device__ __half g_W2o_h[8  * 8192], g_W2o_l[8  * 8192];
__device__ __half g_W1T_h[16 * 8192], g_W1T_l[16 * 8192];

// ---------------- PTX helpers ----------------
__device__ __forceinline__ uint32_t smem_u32(const void* p) {
    uint32_t a;
    asm("{ .reg .u64 t; cvta.to.shared.u64 t, %1; cvt.u32.u64 %0, t; }" : "=r"(a) : "l"(p));
    return a;
}
__device__ __forceinline__ void ldsm4(uint32_t* r, uint32_t a) {
    asm volatile("ldmatrix.sync.aligned.m8n8.x4.shared.b16 {%0,%1,%2,%3}, [%4];"
                 : "=r"(r[0]), "=r"(r[1]), "=r"(r[2]), "=r"(r[3]) : "r"(a));
}
__device__ __forceinline__ void mma_f16(float* c, const uint32_t* a, const uint32_t* b) {
    asm volatile("mma.sync.aligned.m16n8k16.row.col.f32.f16.f16.f32 "
                 "{%0,%1,%2,%3}, {%4,%5,%6,%7}, {%8,%9}, {%0,%1,%2,%3};"
                 : "+f"(c[0]), "+f"(c[1]), "+f"(c[2]), "+f"(c[3])
                 : "r"(a[0]), "r"(a[1]), "r"(a[2]), "r"(a[3]), "r"(b[0]), "r"(b[1]));
}
#define CP_ASYNC16(dst, src) asm volatile("cp.async.cg.shared.global [%0], [%1], 16;" :: "r"(dst), "l"(src) : "memory")
#define CP_COMMIT()          asm volatile("cp.async.commit_group;" ::: "memory")
#define CP_WAIT0()           asm volatile("cp.async.wait_group 0;" ::: "memory")

// ---------------- tile layout: 128B rows, XOR swizzle ----
__device__ __forceinline__ uint32_t swz(int r, int c) {   // c in fp16 elems
    uint32_t off = (uint32_t)((r >> 3) * 1024 + (r & 7) * 128 + c * 2);
    return off ^ ((off >> 3) & 0x70);
}

// smem per CTA = 64KB -> 3 CTAs/SM. A: 64x64 fp16 hi/lo double-buf. B: 64x64 hi/lo double-buf.
#define SM_A(bf, v)  ((bf) * 16384 + (v) * 8192)
#define SM_B(bf, v)  (32768 + (bf) * 16384 + (v) * 8192)
#define SMEM_TOTAL   65536

// ---------------- math ----------------
__device__ __forceinline__ float drho(float s) {
    return (s > 0.f && s < 1.f) ? 1.f : ((s == 0.f || s == 1.f) ? 0.5f : 0.f);
}
__device__ __forceinline__ float adam_step(float pv, float term, float b1t, float b2t,
                                           float& mio, float& vio) {
    float g  = pv - drho(pv) * term;
    float mn = 0.9f   * mio + 0.1f   * g;
    float vn = 0.999f * vio + 0.001f * (g * g);
    mio = mn; vio = vn;
    return pv - 0.01f * ((mn / b1t) / (sqrtf(vn / b2t) + 1e-8f));
}
// clipped split of a scalar -> (hi, lo) fp16
__device__ __forceinline__ void csplit(float x, __half& h, __half& l) {
    float s = __saturatef(x);
    h = __float2half_rn(s);
    l = __float2half_rn(s - __half2float(h));
}
__device__ __forceinline__ uint32_t packh2(__half a, __half b) {
    return ((uint32_t)__half_as_ushort(b) << 16) | __half_as_ushort(a);
}

// ---------------- chunk staging: pure cp.async (A state split + B weights) ------
__device__ __forceinline__ void issue_chunk(uint32_t smb, int bf,
                                            const __half* __restrict__ sH,
                                            const __half* __restrict__ sL, int sstride,
                                            int bm0, int c,
                                            const __half* __restrict__ wH,
                                            const __half* __restrict__ wL, int tid) {
#pragma unroll
    for (int i = 0; i < 2; i++) {
        int idx = tid + i * 256;
        int r = idx >> 3, cc = (idx & 7) * 8;
        size_t so = (size_t)(bm0 + r) * sstride + c * 64 + cc;
        uint32_t d = swz(r, cc);
        CP_ASYNC16(smb + SM_A(bf, 0) + d, sH + so);
        CP_ASYNC16(smb + SM_A(bf, 1) + d, sL + so);
    }
#pragma unroll
    for (int i = 0; i < 2; i++) {
        int e = tid + i * 256;
        CP_ASYNC16(smb + SM_B(bf, 0) + e * 16, wH + (size_t)c * 8192 + e * 8);
        CP_ASYNC16(smb + SM_B(bf, 1) + e * 16, wL + (size_t)c * 8192 + e * 8);
    }
    CP_COMMIT();
}

// ---------------- mainloop: acc += rho(state)[64xK] @ B[Kx64] (3-product fp16) ----
// 256 threads, 8 warps; warp tile 32(m) x 16(n): wm = wid&1, wn = wid>>1.
__device__ __forceinline__ void mainloop(uint32_t smb,
                                         const __half* __restrict__ sH,
                                         const __half* __restrict__ sL, int sstride, int bm0,
                                         const __half* __restrict__ wH,
                                         const __half* __restrict__ wL,
                                         int nchunks, int tid, float acc[2][2][4]) {
    const int lane = tid & 31, wid = tid >> 5, wm = wid & 1, wn = wid >> 1;

    issue_chunk(smb, 0, sH, sL, sstride, bm0, 0, wH, wL, tid);

    for (int c = 0; c < nchunks; ++c) {
        const int p = c & 1;
        CP_WAIT0();
        __syncthreads();                       // buf p staged; all warps past mma(c-1)
        if (c + 1 < nchunks)
            issue_chunk(smb, p ^ 1, sH, sL, sstride, bm0, c + 1, wH, wL, tid);

#pragma unroll
        for (int ks = 0; ks < 4; ++ks) {
            uint32_t Ah[2][4], Al[2][4], Bh[4], Bl[4];
            int ac = ks * 16 + (lane >> 4) * 8;
#pragma unroll
            for (int mt = 0; mt < 2; ++mt) {
                uint32_t o = swz(wm * 32 + mt * 16 + (lane & 15), ac);
                ldsm4(Ah[mt], smb + SM_A(p, 0) + o);
                ldsm4(Al[mt], smb + SM_A(p, 1) + o);
            }
            int bc = ks * 16 + ((lane >> 3) & 1) * 8;
            int br = wn * 16 + ((lane >> 4) & 1) * 8 + (lane & 7);
            {
                uint32_t o = swz(br, bc);
                ldsm4(Bh, smb + SM_B(p, 0) + o);
                ldsm4(Bl, smb + SM_B(p, 1) + o);
            }
#pragma unroll
            for (int mt = 0; mt < 2; ++mt) {
                mma_f16(acc[mt][0], Ah[mt], Bh);      // hh
                mma_f16(acc[mt][1], Ah[mt], Bh + 2);
                mma_f16(acc[mt][0], Ah[mt], Bl);      // hl
                mma_f16(acc[mt][1], Ah[mt], Bl + 2);
                mma_f16(acc[mt][0], Al[mt], Bh);      // lh
                mma_f16(acc[mt][1], Al[mt], Bh + 2);
            }
        }
    }
}

// ---------------- kernels ----------------
__global__ __launch_bounds__(256, 3)
void pre_kernel(const float* __restrict__ b_h) {
    extern __shared__ __align__(1024) char sm[];
    uint32_t smb = smem_u32(sm);
    const int tid = threadIdx.x, lane = tid & 31, wid = tid >> 5;
    const int wm = wid & 1, wn = wid >> 1;
    const int bid = blockIdx.x;
    const int bm0 = (bid >> 3) * 64, nt8 = bid & 7;

    float acc[2][2][4];
#pragma unroll
    for (int a = 0; a < 2; a++)
#pragma unroll
        for (int b = 0; b < 2; b++)
#pragma unroll
            for (int q = 0; q < 4; q++) acc[a][b][q] = 0.f;

    const __half* wH = g_W1T_h + (size_t)(nt8 >> 1) * 4 * 8192 + (nt8 & 1) * 4096;
    const __half* wL = g_W1T_l + (size_t)(nt8 >> 1) * 4 * 8192 + (nt8 & 1) * 4096;
    mainloop(smb, g_xch, g_xcl, INPUT, bm0, wH, wL, 4, tid, acc);

#pragma unroll
    for (int mt = 0; mt < 2; ++mt)
#pragma unroll
        for (int nt = 0; nt < 2; ++nt)
#pragma unroll
            for (int rr = 0; rr < 2; ++rr) {
                int r = bm0 + wm * 32 + mt * 16 + rr * 8 + (lane >> 2);
                int col = nt8 * 64 + wn * 16 + nt * 8 + (lane & 3) * 2;
                float2 bh = *reinterpret_cast<const float2*>(&b_h[col]);
                float2 out;
                out.x = acc[mt][nt][rr * 2]     + bh.x;
                out.y = acc[mt][nt][rr * 2 + 1] + bh.y;
                *reinterpret_cast<float2*>(&g_A[(size_t)r * HIDDEN + col]) = out;
            }
}

__global__ __launch_bounds__(256, 3)
void step_kernel(const float* __restrict__ hr_o, const __half* __restrict__ hch_o,
                 const __half* __restrict__ hcl_o,
                 float* __restrict__ hr_n, __half* __restrict__ hch_n, __half* __restrict__ hcl_n,
                 const float* __restrict__ or_o, const __half* __restrict__ och_o,
                 const __half* __restrict__ ocl_o,
                 float* __restrict__ or_n, __half* __restrict__ och_n, __half* __restrict__ ocl_n,
                 const float* __restrict__ b_o, float b1t, float b2t) {
    extern __shared__ __align__(1024) char sm[];
    uint32_t smb = smem_u32(sm);
    const int tid = threadIdx.x, lane = tid & 31, wid = tid >> 5;
    const int wm = wid & 1, wn = wid >> 1;
    const int bid = blockIdx.x;

    float acc[2][2][4];
#pragma unroll
    for (int a = 0; a < 2; a++)
#pragma unroll
        for (int b = 0; b < 2; b++)
#pragma unroll
            for (int q = 0; q < 4; q++) acc[a][b][q] = 0.f;

    if (bid < 512) {
        // -------- o update: D = rho(h_old) @ W2o (K=512, 8 chunks); N-half nsub ----
        const int bm0 = (bid >> 1) * 64, nsub = bid & 1;
        const __half* wH = g_W2o_h + nsub * 4096;
        const __half* wL = g_W2o_l + nsub * 4096;
        mainloop(smb, hch_o, hcl_o, HIDDEN, bm0, wH, wL, 8, tid, acc);
#pragma unroll
        for (int mt = 0; mt < 2; ++mt)
#pragma unroll
            for (int nt = 0; nt < 2; ++nt)
#pragma unroll
                for (int rr = 0; rr < 2; ++rr) {
                    int r = bm0 + wm * 32 + mt * 16 + rr * 8 + (lane >> 2);
                    int cc = nsub * 64 + wn * 16 + nt * 8 + (lane & 3) * 2;
                    size_t idx = (size_t)r * OUTPUT + cc;
                    float2 bo = *reinterpret_cast<const float2*>(&b_o[cc]);
                    float2 pv = *reinterpret_cast<const float2*>(&or_o[idx]);
                    float2 mv = *reinterpret_cast<const float2*>(&g_mo[idx]);
                    float2 vv = *reinterpret_cast<const float2*>(&g_vo[idx]);
                    float2 pn;
                    pn.x = adam_step(pv.x, bo.x + acc[mt][nt][rr * 2],     b1t, b2t, mv.x, vv.x);
                    pn.y = adam_step(pv.y, bo.y + acc[mt][nt][rr * 2 + 1], b1t, b2t, mv.y, vv.y);
                    *reinterpret_cast<float2*>(&g_mo[idx]) = mv;
                    *reinterpret_cast<float2*>(&g_vo[idx]) = vv;
                    *reinterpret_cast<float2*>(&or_n[idx]) = pn;
                    __half hx, lx, hy, ly;
                    csplit(pn.x, hx, lx); csplit(pn.y, hy, ly);
                    *reinterpret_cast<uint32_t*>(&och_n[idx]) = packh2(hx, hy);
                    *reinterpret_cast<uint32_t*>(&ocl_n[idx]) = packh2(lx, ly);
                }
    } else {
        // -------- h update: D = rho(o_old) @ W2h (K=128, 2 chunks); term = A + D ----
        const int idx0 = bid - 512;
        const int bm0 = (idx0 >> 3) * 64, nt8 = idx0 & 7;
        const __half* wH = g_W2h_h + (size_t)(nt8 >> 1) * 2 * 8192 + (nt8 & 1) * 4096;
        const __half* wL = g_W2h_l + (size_t)(nt8 >> 1) * 2 * 8192 + (nt8 & 1) * 4096;
        mainloop(smb, och_o, ocl_o, OUTPUT, bm0, wH, wL, 2, tid, acc);
#pragma unroll
        for (int mt = 0; mt < 2; ++mt)
#pragma unroll
            for (int nt = 0; nt < 2; ++nt)
#pragma unroll
                for (int rr = 0; rr < 2; ++rr) {
                    int r = bm0 + wm * 32 + mt * 16 + rr * 8 + (lane >> 2);
                    int col = nt8 * 64 + wn * 16 + nt * 8 + (lane & 3) * 2;
                    size_t idx = (size_t)r * HIDDEN + col;
                    float2 av = *reinterpret_cast<const float2*>(&g_A[idx]);
                    float2 pv = *reinterpret_cast<const float2*>(&hr_o[idx]);
                    float2 mv = *reinterpret_cast<const float2*>(&g_mh[idx]);
                    float2 vv = *reinterpret_cast<const float2*>(&g_vh[idx]);
                    float2 pn;
                    pn.x = adam_step(pv.x, av.x + acc[mt][nt][rr * 2],     b1t, b2t, mv.x, vv.x);
                    pn.y = adam_step(pv.y, av.y + acc[mt][nt][rr * 2 + 1], b1t, b2t, mv.y, vv.y);
                    *reinterpret_cast<float2*>(&g_mh[idx]) = mv;
                    *reinterpret_cast<float2*>(&g_vh[idx]) = vv;
                    *reinterpret_cast<float2*>(&hr_n[idx]) = pn;
                    __half hx, lx, hy, ly;
                    csplit(pn.x, hx, lx); csplit(pn.y, hy, ly);
                    *reinterpret_cast<uint32_t*>(&hch_n[idx]) = packh2(hx, hy);
                    *reinterpret_cast<uint32_t*>(&hcl_n[idx]) = packh2(lx, ly);
                }
    }
}

// ---------------- prep kernels ----------------
__global__ void init_zero_kernel() {
    int i = blockIdx.x * blockDim.x + threadIdx.x;
    const int NH4 = BATCH * HIDDEN / 4, NO4 = BATCH * OUTPUT / 4;
    float4 z4 = make_float4(0.f, 0.f, 0.f, 0.f);
    uint2 z2 = make_uint2(0u, 0u);
    if (i < NH4) {
        reinterpret_cast<float4*>(g_hr0)[i] = z4;
        reinterpret_cast<float4*>(g_mh)[i]  = z4;
        reinterpret_cast<float4*>(g_vh)[i]  = z4;
        reinterpret_cast<uint2*>(g_hch0)[i] = z2;
        reinterpret_cast<uint2*>(g_hcl0)[i] = z2;
    }
    if (i < NO4) {
        reinterpret_cast<float4*>(g_or0)[i] = z4;
        reinterpret_cast<float4*>(g_mo)[i]  = z4;
        reinterpret_cast<float4*>(g_vo)[i]  = z4;
        reinterpret_cast<uint2*>(g_och0)[i] = z2;
        reinterpret_cast<uint2*>(g_ocl0)[i] = z2;
    }
}

__global__ void prep_x(const float* __restrict__ x) {
    int t = blockIdx.x * blockDim.x + threadIdx.x;      // float4 index
    float4 v = reinterpret_cast<const float4*>(x)[t];
    __half h0, l0, h1, l1, h2, l2, h3, l3;
    csplit(v.x, h0, l0); csplit(v.y, h1, l1);
    csplit(v.z, h2, l2); csplit(v.w, h3, l3);
    uint2 H, L;
    H.x = packh2(h0, h1); H.y = packh2(h2, h3);
    L.x = packh2(l0, l1); L.y = packh2(l2, l3);
    reinterpret_cast<uint2*>(g_xch)[t] = H;
    reinterpret_cast<uint2*>(g_xcl)[t] = L;
}

__global__ void prep_weights(const float* __restrict__ W1, const float* __restrict__ W2) {
    int t = blockIdx.x * blockDim.x + threadIdx.x;   // 0 .. 262143
    float v;
    __half *ph, *pl;
    int tile, r, cl;
    if (t < 65536) {                    // W2h: B[n][k] = W2[n][k]
        tile = t >> 13; int e = t & 8191; r = e >> 6; cl = e & 63;
        int tn = tile >> 1, kc = tile & 1;
        v = W2[(size_t)(tn * 128 + r) * OUTPUT + kc * 64 + cl];
        ph = g_W2h_h; pl = g_W2h_l;
    } else if (t < 131072) {            // W2o: B[n][k] = W2[k][n]
        int t2 = t - 65536;
        tile = t2 >> 13; int e = t2 & 8191; r = e >> 6; cl = e & 63;
        v = W2[(size_t)(tile * 64 + cl) * OUTPUT + r];
        ph = g_W2o_h; pl = g_W2o_l;
    } else {                            // W1T: B[n][k] = W1[k][n]
        int t3 = t - 131072;
        tile = t3 >> 13; int e = t3 & 8191; r = e >> 6; cl = e & 63;
        int tn = tile >> 2, kc = tile & 3;
        v = W1[(size_t)(kc * 64 + cl) * HIDDEN + tn * 128 + r];
        ph = g_W1T_h; pl = g_W1T_l;
    }
    __half h = __float2half_rn(v);
    __half l = __float2half_rn(v - __half2float(h));
    uint32_t off = swz(r, cl);
    size_t tb = (size_t)tile * 16384;
    *reinterpret_cast<__half*>(reinterpret_cast<char*>(ph) + tb + off) = h;
    *reinterpret_cast<__half*>(reinterpret_cast<char*>(pl) + tb + off) = l;
}

// ---------------- launch ----------------
extern "C" void kernel_launch(void* const* d_in, const int* in_sizes, int n_in,
                              void* d_out, int out_size) {
    (void)in_sizes; (void)n_in; (void)out_size;
    const float* x   = (const float*)d_in[0];
    const float* W1  = (const float*)d_in[1];
    const float* W2  = (const float*)d_in[2];
    const float* b_h = (const float*)d_in[4];
    const float* b_o = (const float*)d_in[5];

    cudaFuncSetAttribute(pre_kernel,  cudaFuncAttributeMaxDynamicSharedMemorySize, SMEM_TOTAL);
    cudaFuncSetAttribute(step_kernel, cudaFuncAttributeMaxDynamicSharedMemorySize, SMEM_TOTAL);

    float *hr0, *hr1, *or0;
    __half *hch0, *hcl0, *hch1, *hcl1, *och0, *ocl0, *och1, *ocl1;
    cudaGetSymbolAddress((void**)&hr0,  g_hr0);
    cudaGetSymbolAddress((void**)&hr1,  g_hr1);
    cudaGetSymbolAddress((void**)&or0,  g_or0);
    cudaGetSymbolAddress((void**)&hch0, g_hch0);
    cudaGetSymbolAddress((void**)&hcl0, g_hcl0);
    cudaGetSymbolAddress((void**)&hch1, g_hch1);
    cudaGetSymbolAddress((void**)&hcl1, g_hcl1);
    cudaGetSymbolAddress((void**)&och0, g_och0);
    cudaGetSymbolAddress((void**)&ocl0, g_ocl0);
    cudaGetSymbolAddress((void**)&och1, g_och1);
    cudaGetSymbolAddress((void**)&ocl1, g_ocl1);

    init_zero_kernel<<<(BATCH * HIDDEN / 4 + 255) / 256, 256>>>();
    prep_x<<<BATCH * INPUT / 4 / 256, 256>>>(x);
    prep_weights<<<262144 / 256, 256>>>(W1, W2);
    pre_kernel<<<2048, 256, SMEM_TOTAL>>>(b_h);

    float*  hr[2]  = {hr0, hr1};
    __half* hch[2] = {hch0, hch1};
    __half* hcl[2] = {hcl0, hcl1};
    float*  orr[2] = {or0, (float*)d_out};   // t odd writes orr[1]; t=15 -> d_out
    __half* och[2] = {och0, och1};
    __half* ocl[2] = {ocl0, ocl1};

    for (int t = 1; t <= NITER; ++t) {
        int p = (t - 1) & 1;
        float b1t = 1.0f - powf(0.9f,   (float)t);
        float b2t = 1.0f - powf(0.999f, (float)t);
        step_kernel<<<2560, 256, SMEM_TOTAL>>>(
            hr[p], hch[p], hcl[p], hr[1 - p], hch[1 - p], hcl[1 - p],
            orr[p], och[p], ocl[p], orr[1 - p], och[1 - p], ocl[1 - p],
            b_o, b1t, b2t);
    }
}

// round 10
// speedup vs baseline: 2.1930x; 1.0834x over previous
#include <cuda_runtime.h>
#include <cuda_fp16.h>
#include <math.h>
#include <stdint.h>

#define BATCH  16384
#define INPUT  256
#define HIDDEN 512
#define OUTPUT 128
#define NITER  15

// ---------------- device scratch ----------------
__device__ float g_A  [BATCH * HIDDEN];
__device__ float g_hr0[BATCH * HIDDEN], g_hr1[BATCH * HIDDEN];   // raw h (Adam pv)
__device__ float g_or0[BATCH * OUTPUT];                          // raw o buf0 (buf1 = d_out)
// fp32 Adam state interleaved per 2 elements: (m0, v0, m1, v1)
__device__ float4 g_mvh[BATCH * HIDDEN / 2];
__device__ float4 g_mvo[BATCH * OUTPUT / 2];
// rho-clipped fp16 hi/lo split state (GEMM operand form)
__device__ __half g_hch0[BATCH * HIDDEN], g_hcl0[BATCH * HIDDEN];
__device__ __half g_hch1[BATCH * HIDDEN], g_hcl1[BATCH * HIDDEN];
__device__ __half g_och0[BATCH * OUTPUT], g_ocl0[BATCH * OUTPUT];
__device__ __half g_och1[BATCH * OUTPUT], g_ocl1[BATCH * OUTPUT];
__device__ __half g_xch [BATCH * INPUT],  g_xcl [BATCH * INPUT];

// 2-way-split fp16 weight tiles (hi/lo). Tile = 128 n-rows x 64 k-cols, pre-swizzled.
__device__ __half g_W2h_h[8  * 8192], g_W2h_l[8  * 8192];
__device__ __half g_W2o_h[8  * 8192], g_W2o_l[8  * 8192];
__device__ __half g_W1T_h[16 * 8192], g_W1T_l[16 * 8192];

// ---------------- PTX helpers ----------------
__device__ __forceinline__ uint32_t smem_u32(const void* p) {
    uint32_t a;
    asm("{ .reg .u64 t; cvta.to.shared.u64 t, %1; cvt.u32.u64 %0, t; }" : "=r"(a) : "l"(p));
    return a;
}
__device__ __forceinline__ void ldsm4(uint32_t* r, uint32_t a) {
    asm volatile("ldmatrix.sync.aligned.m8n8.x4.shared.b16 {%0,%1,%2,%3}, [%4];"
                 : "=r"(r[0]), "=r"(r[1]), "=r"(r[2]), "=r"(r[3]) : "r"(a));
}
__device__ __forceinline__ void mma_f16(float* c, const uint32_t* a, const uint32_t* b) {
    asm volatile("mma.sync.aligned.m16n8k16.row.col.f32.f16.f16.f32 "
                 "{%0,%1,%2,%3}, {%4,%5,%6,%7}, {%8,%9}, {%0,%1,%2,%3};"
                 : "+f"(c[0]), "+f"(c[1]), "+f"(c[2]), "+f"(c[3])
                 : "r"(a[0]), "r"(a[1]), "r"(a[2]), "r"(a[3]), "r"(b[0]), "r"(b[1]));
}
#define CP_ASYNC16(dst, src) asm volatile("cp.async.cg.shared.global [%0], [%1], 16;" :: "r"(dst), "l"(src) : "memory")
#define CP_COMMIT()          asm volatile("cp.async.commit_group;" ::: "memory")
#define CP_WAIT0()           asm volatile("cp.async.wait_group 0;" ::: "memory")

// ---------------- tile layout: 128B rows, XOR swizzle ----
__device__ __forceinline__ uint32_t swz(int r, int c) {   // c in fp16 elems
    uint32_t off = (uint32_t)((r >> 3) * 1024 + (r & 7) * 128 + c * 2);
    return off ^ ((off >> 3) & 0x70);
}

// smem per CTA = 64KB -> 3 CTAs/SM. A: 64x64 fp16 hi/lo double-buf. B: 64x64 hi/lo double-buf.
#define SM_A(bf, v)  ((bf) * 16384 + (v) * 8192)
#define SM_B(bf, v)  (32768 + (bf) * 16384 + (v) * 8192)
#define SMEM_TOTAL   65536

// ---------------- math ----------------
__device__ __forceinline__ float drho(float s) {
    return (s > 0.f && s < 1.f) ? 1.f : ((s == 0.f || s == 1.f) ? 0.5f : 0.f);
}
// Adam with precomputed 1/(1-b1^t), 1/(1-b2^t); single fast divide.
__device__ __forceinline__ float adam_step(float pv, float term, float ib1t, float ib2t,
                                           float& mio, float& vio) {
    float g  = pv - drho(pv) * term;
    float mn = 0.9f   * mio + 0.1f   * g;
    float vn = 0.999f * vio + 0.001f * (g * g);
    mio = mn; vio = vn;
    float mh = mn * ib1t;
    float vh = vn * ib2t;
    return pv - 0.01f * __fdividef(mh, sqrtf(vh) + 1e-8f);
}
// clipped split of a scalar -> (hi, lo) fp16
__device__ __forceinline__ void csplit(float x, __half& h, __half& l) {
    float s = __saturatef(x);
    h = __float2half_rn(s);
    l = __float2half_rn(s - __half2float(h));
}
__device__ __forceinline__ uint32_t packh2(__half a, __half b) {
    return ((uint32_t)__half_as_ushort(b) << 16) | __half_as_ushort(a);
}

// ---------------- chunk staging: pure cp.async (A state split + B weights) ------
__device__ __forceinline__ void issue_chunk(uint32_t smb, int bf,
                                            const __half* __restrict__ sH,
                                            const __half* __restrict__ sL, int sstride,
                                            int bm0, int c,
                                            const __half* __restrict__ wH,
                                            const __half* __restrict__ wL, int tid) {
#pragma unroll
    for (int i = 0; i < 2; i++) {
        int idx = tid + i * 256;
        int r = idx >> 3, cc = (idx & 7) * 8;
        size_t so = (size_t)(bm0 + r) * sstride + c * 64 + cc;
        uint32_t d = swz(r, cc);
        CP_ASYNC16(smb + SM_A(bf, 0) + d, sH + so);
        CP_ASYNC16(smb + SM_A(bf, 1) + d, sL + so);
    }
#pragma unroll
    for (int i = 0; i < 2; i++) {
        int e = tid + i * 256;
        CP_ASYNC16(smb + SM_B(bf, 0) + e * 16, wH + (size_t)c * 8192 + e * 8);
        CP_ASYNC16(smb + SM_B(bf, 1) + e * 16, wL + (size_t)c * 8192 + e * 8);
    }
    CP_COMMIT();
}

// ---------------- mainloop: acc += rho(state)[64xK] @ B[Kx64] (3-product fp16) ----
// 256 threads, 8 warps; warp tile 32(m) x 16(n): wm = wid&1, wn = wid>>1.
__device__ __forceinline__ void mainloop(uint32_t smb,
                                         const __half* __restrict__ sH,
                                         const __half* __restrict__ sL, int sstride, int bm0,
                                         const __half* __restrict__ wH,
                                         const __half* __restrict__ wL,
                                         int nchunks, int tid, float acc[2][2][4]) {
    const int lane = tid & 31, wid = tid >> 5, wm = wid & 1, wn = wid >> 1;

    issue_chunk(smb, 0, sH, sL, sstride, bm0, 0, wH, wL, tid);

    for (int c = 0; c < nchunks; ++c) {
        const int p = c & 1;
        CP_WAIT0();
        __syncthreads();                       // buf p staged; all warps past mma(c-1)
        if (c + 1 < nchunks)
            issue_chunk(smb, p ^ 1, sH, sL, sstride, bm0, c + 1, wH, wL, tid);

#pragma unroll
        for (int ks = 0; ks < 4; ++ks) {
            uint32_t Ah[2][4], Al[2][4], Bh[4], Bl[4];
            int ac = ks * 16 + (lane >> 4) * 8;
#pragma unroll
            for (int mt = 0; mt < 2; ++mt) {
                uint32_t o = swz(wm * 32 + mt * 16 + (lane & 15), ac);
                ldsm4(Ah[mt], smb + SM_A(p, 0) + o);
                ldsm4(Al[mt], smb + SM_A(p, 1) + o);
            }
            int bc = ks * 16 + ((lane >> 3) & 1) * 8;
            int br = wn * 16 + ((lane >> 4) & 1) * 8 + (lane & 7);
            {
                uint32_t o = swz(br, bc);
                ldsm4(Bh, smb + SM_B(p, 0) + o);
                ldsm4(Bl, smb + SM_B(p, 1) + o);
            }
#pragma unroll
            for (int mt = 0; mt < 2; ++mt) {
                mma_f16(acc[mt][0], Ah[mt], Bh);      // hh
                mma_f16(acc[mt][1], Ah[mt], Bh + 2);
                mma_f16(acc[mt][0], Ah[mt], Bl);      // hl
                mma_f16(acc[mt][1], Ah[mt], Bl + 2);
                mma_f16(acc[mt][0], Al[mt], Bh);      // lh
                mma_f16(acc[mt][1], Al[mt], Bh + 2);
            }
        }
    }
}

// Adam on a float2 with interleaved fp32 (m0,v0,m1,v1) state. idx even.
__device__ __forceinline__ float2 adam2_f32(float4* __restrict__ mv_arr, size_t idx,
                                            float2 pv, float2 term,
                                            float ib1t, float ib2t) {
    float4 mv = mv_arr[idx >> 1];
    float2 pn;
    pn.x = adam_step(pv.x, term.x, ib1t, ib2t, mv.x, mv.y);
    pn.y = adam_step(pv.y, term.y, ib1t, ib2t, mv.z, mv.w);
    mv_arr[idx >> 1] = mv;
    return pn;
}

// ---------------- kernels ----------------
__global__ __launch_bounds__(256, 3)
void pre_kernel(const float* __restrict__ b_h) {
    extern __shared__ __align__(1024) char sm[];
    uint32_t smb = smem_u32(sm);
    const int tid = threadIdx.x, lane = tid & 31, wid = tid >> 5;
    const int wm = wid & 1, wn = wid >> 1;
    const int bid = blockIdx.x;
    const int bm0 = (bid >> 3) * 64, nt8 = bid & 7;

    float acc[2][2][4];
#pragma unroll
    for (int a = 0; a < 2; a++)
#pragma unroll
        for (int b = 0; b < 2; b++)
#pragma unroll
            for (int q = 0; q < 4; q++) acc[a][b][q] = 0.f;

    const __half* wH = g_W1T_h + (size_t)(nt8 >> 1) * 4 * 8192 + (nt8 & 1) * 4096;
    const __half* wL = g_W1T_l + (size_t)(nt8 >> 1) * 4 * 8192 + (nt8 & 1) * 4096;
    mainloop(smb, g_xch, g_xcl, INPUT, bm0, wH, wL, 4, tid, acc);

#pragma unroll
    for (int mt = 0; mt < 2; ++mt)
#pragma unroll
        for (int nt = 0; nt < 2; ++nt)
#pragma unroll
            for (int rr = 0; rr < 2; ++rr) {
                int r = bm0 + wm * 32 + mt * 16 + rr * 8 + (lane >> 2);
                int col = nt8 * 64 + wn * 16 + nt * 8 + (lane & 3) * 2;
                float2 bh = *reinterpret_cast<const float2*>(&b_h[col]);
                float2 out;
                out.x = acc[mt][nt][rr * 2]     + bh.x;
                out.y = acc[mt][nt][rr * 2 + 1] + bh.y;
                *reinterpret_cast<float2*>(&g_A[(size_t)r * HIDDEN + col]) = out;
            }
}

__global__ __launch_bounds__(256, 3)
void step_kernel(const float* __restrict__ hr_o, const __half* __restrict__ hch_o,
                 const __half* __restrict__ hcl_o,
                 float* __restrict__ hr_n, __half* __restrict__ hch_n, __half* __restrict__ hcl_n,
                 const float* __restrict__ or_o, const __half* __restrict__ och_o,
                 const __half* __restrict__ ocl_o,
                 float* __restrict__ or_n, __half* __restrict__ och_n, __half* __restrict__ ocl_n,
                 const float* __restrict__ b_o, float ib1t, float ib2t) {
    extern __shared__ __align__(1024) char sm[];
    uint32_t smb = smem_u32(sm);
    const int tid = threadIdx.x, lane = tid & 31, wid = tid >> 5;
    const int wm = wid & 1, wn = wid >> 1;
    const int bid = blockIdx.x;

    float acc[2][2][4];
#pragma unroll
    for (int a = 0; a < 2; a++)
#pragma unroll
        for (int b = 0; b < 2; b++)
#pragma unroll
            for (int q = 0; q < 4; q++) acc[a][b][q] = 0.f;

    if (bid < 512) {
        // -------- o update: D = rho(h_old) @ W2o (K=512, 8 chunks); N-half nsub ----
        const int bm0 = (bid >> 1) * 64, nsub = bid & 1;
        const __half* wH = g_W2o_h + nsub * 4096;
        const __half* wL = g_W2o_l + nsub * 4096;
        mainloop(smb, hch_o, hcl_o, HIDDEN, bm0, wH, wL, 8, tid, acc);
#pragma unroll
        for (int mt = 0; mt < 2; ++mt)
#pragma unroll
            for (int nt = 0; nt < 2; ++nt)
#pragma unroll
                for (int rr = 0; rr < 2; ++rr) {
                    int r = bm0 + wm * 32 + mt * 16 + rr * 8 + (lane >> 2);
                    int cc = nsub * 64 + wn * 16 + nt * 8 + (lane & 3) * 2;
                    size_t idx = (size_t)r * OUTPUT + cc;
                    float2 bo = *reinterpret_cast<const float2*>(&b_o[cc]);
                    float2 pv = *reinterpret_cast<const float2*>(&or_o[idx]);
                    float2 term;
                    term.x = bo.x + acc[mt][nt][rr * 2];
                    term.y = bo.y + acc[mt][nt][rr * 2 + 1];
                    float2 pn = adam2_f32(g_mvo, idx, pv, term, ib1t, ib2t);
                    *reinterpret_cast<float2*>(&or_n[idx]) = pn;
                    __half hx, lx, hy, ly;
                    csplit(pn.x, hx, lx); csplit(pn.y, hy, ly);
                    *reinterpret_cast<uint32_t*>(&och_n[idx]) = packh2(hx, hy);
                    *reinterpret_cast<uint32_t*>(&ocl_n[idx]) = packh2(lx, ly);
                }
    } else {
        // -------- h update: D = rho(o_old) @ W2h (K=128, 2 chunks); term = A + D ----
        const int idx0 = bid - 512;
        const int bm0 = (idx0 >> 3) * 64, nt8 = idx0 & 7;
        const __half* wH = g_W2h_h + (size_t)(nt8 >> 1) * 2 * 8192 + (nt8 & 1) * 4096;
        const __half* wL = g_W2h_l + (size_t)(nt8 >> 1) * 2 * 8192 + (nt8 & 1) * 4096;
        mainloop(smb, och_o, ocl_o, OUTPUT, bm0, wH, wL, 2, tid, acc);
#pragma unroll
        for (int mt = 0; mt < 2; ++mt)
#pragma unroll
            for (int nt = 0; nt < 2; ++nt)
#pragma unroll
                for (int rr = 0; rr < 2; ++rr) {
                    int r = bm0 + wm * 32 + mt * 16 + rr * 8 + (lane >> 2);
                    int col = nt8 * 64 + wn * 16 + nt * 8 + (lane & 3) * 2;
                    size_t idx = (size_t)r * HIDDEN + col;
                    float2 av = *reinterpret_cast<const float2*>(&g_A[idx]);
                    float2 pv = *reinterpret_cast<const float2*>(&hr_o[idx]);
                    float2 term;
                    term.x = av.x + acc[mt][nt][rr * 2];
                    term.y = av.y + acc[mt][nt][rr * 2 + 1];
                    float2 pn = adam2_f32(g_mvh, idx, pv, term, ib1t, ib2t);
                    *reinterpret_cast<float2*>(&hr_n[idx]) = pn;
                    __half hx, lx, hy, ly;
                    csplit(pn.x, hx, lx); csplit(pn.y, hy, ly);
                    *reinterpret_cast<uint32_t*>(&hch_n[idx]) = packh2(hx, hy);
                    *reinterpret_cast<uint32_t*>(&hcl_n[idx]) = packh2(lx, ly);
                }
    }
}

// ---------------- prep kernels ----------------
__global__ void init_zero_kernel() {
    int i = blockIdx.x * blockDim.x + threadIdx.x;
    const int NH4 = BATCH * HIDDEN / 4, NO4 = BATCH * OUTPUT / 4;
    float4 z4 = make_float4(0.f, 0.f, 0.f, 0.f);
    uint2 z2 = make_uint2(0u, 0u);
    if (i < NH4) {
        reinterpret_cast<float4*>(g_hr0)[i] = z4;
        g_mvh[i * 2]     = z4;
        g_mvh[i * 2 + 1] = z4;
        reinterpret_cast<uint2*>(g_hch0)[i] = z2;
        reinterpret_cast<uint2*>(g_hcl0)[i] = z2;
    }
    if (i < NO4) {
        reinterpret_cast<float4*>(g_or0)[i] = z4;
        g_mvo[i * 2]     = z4;
        g_mvo[i * 2 + 1] = z4;
        reinterpret_cast<uint2*>(g_och0)[i] = z2;
        reinterpret_cast<uint2*>(g_ocl0)[i] = z2;
    }
}

__global__ void prep_x(const float* __restrict__ x) {
    int t = blockIdx.x * blockDim.x + threadIdx.x;      // float4 index
    float4 v = reinterpret_cast<const float4*>(x)[t];
    __half h0, l0, h1, l1, h2, l2, h3, l3;
    csplit(v.x, h0, l0); csplit(v.y, h1, l1);
    csplit(v.z, h2, l2); csplit(v.w, h3, l3);
    uint2 H, L;
    H.x = packh2(h0, h1); H.y = packh2(h2, h3);
    L.x = packh2(l0, l1); L.y = packh2(l2, l3);
    reinterpret_cast<uint2*>(g_xch)[t] = H;
    reinterpret_cast<uint2*>(g_xcl)[t] = L;
}

__global__ void prep_weights(const float* __restrict__ W1, const float* __restrict__ W2) {
    int t = blockIdx.x * blockDim.x + threadIdx.x;   // 0 .. 262143
    float v;
    __half *ph, *pl;
    int tile, r, cl;
    if (t < 65536) {                    // W2h: B[n][k] = W2[n][k]
        tile = t >> 13; int e = t & 8191; r = e >> 6; cl = e & 63;
        int tn = tile >> 1, kc = tile & 1;
        v = W2[(size_t)(tn * 128 + r) * OUTPUT + kc * 64 + cl];
        ph = g_W2h_h; pl = g_W2h_l;
    } else if (t < 131072) {            // W2o: B[n][k] = W2[k][n]
        int t2 = t - 65536;
        tile = t2 >> 13; int e = t2 & 8191; r = e >> 6; cl = e & 63;
        v = W2[(size_t)(tile * 64 + cl) * OUTPUT + r];
        ph = g_W2o_h; pl = g_W2o_l;
    } else {                            // W1T: B[n][k] = W1[k][n]
        int t3 = t - 131072;
        tile = t3 >> 13; int e = t3 & 8191; r = e >> 6; cl = e & 63;
        int tn = tile >> 2, kc = tile & 3;
        v = W1[(size_t)(kc * 64 + cl) * HIDDEN + tn * 128 + r];
        ph = g_W1T_h; pl = g_W1T_l;
    }
    __half h = __float2half_rn(v);
    __half l = __float2half_rn(v - __half2float(h));
    uint32_t off = swz(r, cl);
    size_t tb = (size_t)tile * 16384;
    *reinterpret_cast<__half*>(reinterpret_cast<char*>(ph) + tb + off) = h;
    *reinterpret_cast<__half*>(reinterpret_cast<char*>(pl) + tb + off) = l;
}

// ---------------- launch ----------------
extern "C" void kernel_launch(void* const* d_in, const int* in_sizes, int n_in,
                              void* d_out, int out_size) {
    (void)in_sizes; (void)n_in; (void)out_size;
    const float* x   = (const float*)d_in[0];
    const float* W1  = (const float*)d_in[1];
    const float* W2  = (const float*)d_in[2];
    const float* b_h = (const float*)d_in[4];
    const float* b_o = (const float*)d_in[5];

    cudaFuncSetAttribute(pre_kernel,  cudaFuncAttributeMaxDynamicSharedMemorySize, SMEM_TOTAL);
    cudaFuncSetAttribute(step_kernel, cudaFuncAttributeMaxDynamicSharedMemorySize, SMEM_TOTAL);

    float *hr0, *hr1, *or0;
    __half *hch0, *hcl0, *hch1, *hcl1, *och0, *ocl0, *och1, *ocl1;
    cudaGetSymbolAddress((void**)&hr0,  g_hr0);
    cudaGetSymbolAddress((void**)&hr1,  g_hr1);
    cudaGetSymbolAddress((void**)&or0,  g_or0);
    cudaGetSymbolAddress((void**)&hch0, g_hch0);
    cudaGetSymbolAddress((void**)&hcl0, g_hcl0);
    cudaGetSymbolAddress((void**)&hch1, g_hch1);
    cudaGetSymbolAddress((void**)&hcl1, g_hcl1);
    cudaGetSymbolAddress((void**)&och0, g_och0);
    cudaGetSymbolAddress((void**)&ocl0, g_ocl0);
    cudaGetSymbolAddress((void**)&och1, g_och1);
    cudaGetSymbolAddress((void**)&ocl1, g_ocl1);

    init_zero_kernel<<<(BATCH * HIDDEN / 4 + 255) / 256, 256>>>();
    prep_x<<<BATCH * INPUT / 4 / 256, 256>>>(x);
    prep_weights<<<262144 / 256, 256>>>(W1, W2);
    pre_kernel<<<2048, 256, SMEM_TOTAL>>>(b_h);

    float*  hr[2]  = {hr0, hr1};
    __half* hch[2] = {hch0, hch1};
    __half* hcl[2] = {hcl0, hcl1};
    float*  orr[2] = {or0, (float*)d_out};   // t odd writes orr[1]; t=15 -> d_out
    __half* och[2] = {och0, och1};
    __half* ocl[2] = {ocl0, ocl1};

    for (int t = 1; t <= NITER; ++t) {
        int p = (t - 1) & 1;
        float ib1t = 1.0f / (1.0f - powf(0.9f,   (float)t));
        float ib2t = 1.0f / (1.0f - powf(0.999f, (float)t));
        step_kernel<<<2560, 256, SMEM_TOTAL>>>(
            hr[p], hch[p], hcl[p], hr[1 - p], hch[1 - p], hcl[1 - p],
            orr[p], och[p], ocl[p], orr[1 - p], och[1 - p], ocl[1 - p],
            b_o, ib1t, ib2t);
    }
}